// round 9
// baseline (speedup 1.0000x reference)
#include <cuda_runtime.h>
#include <cstdint>

// ---------------- problem constants ----------------
#define NN 16
#define CC 64
#define HW 3136       // 56*56
#define WID 56

// ---------------- device scratch ----------------
__device__ float g_maxabs_x, g_maxw1, g_maxw2, g_max_r1, g_max_r2;
__device__ float g_part[512];
__device__ unsigned g_qxp[NN*16*HW];     // packed int8 qx: (n, c4, hw), byte j = channel 4*c4+j
__device__ float    g_t1 [NN*CC*HW];     // bn1 output (pre-relu), fp32
__device__ unsigned g_qw1p[9216];        // packed weights: [c4][pos][o]
__device__ unsigned g_qw2p[9216];
__device__ int g_wsum1[4608], g_wsum2[4608];     // [cb][pos], cb = c*8+bit
__device__ int g_stats1[9*512], g_stats2[9*512]; // 9 stats x 512 channel-bits

__device__ __forceinline__ void atomicMaxF(float* a, float v) {
    atomicMax((int*)a, __float_as_int(v));   // valid for non-negative floats
}
__device__ __forceinline__ int dp4a_ss(unsigned a, unsigned b, int c) {
    int r; asm("dp4a.s32.s32 %0, %1, %2, %3;" : "=r"(r) : "r"(a), "r"(b), "r"(c)); return r;
}
__device__ __forceinline__ int dp4a_us(unsigned a, unsigned b, int c) {
    int r; asm("dp4a.u32.s32 %0, %1, %2, %3;" : "=r"(r) : "r"(a), "r"(b), "r"(c)); return r;
}
template<int PASS>
__device__ __forceinline__ int DP(unsigned a, unsigned b, int c) {
    return (PASS == 1) ? dp4a_ss(a, b, c) : dp4a_us(a, b, c);
}

// ---------------- reduceA: partial max|x| (0..511), max|w| (512,513), init (514)
__global__ void reduceA(const float4* __restrict__ x,
                        const float* __restrict__ w1, const float* __restrict__ w2) {
    int b = blockIdx.x;
    if (b == 514) {
        if (threadIdx.x == 0) { g_max_r1 = 0.f; g_max_r2 = 0.f; }
        for (int i = threadIdx.x; i < 4608; i += 256) { g_stats1[i] = 0; g_stats2[i] = 0; }
        return;
    }
    float m = 0.f;
    if (b < 512) {
        const int n4 = NN*CC*HW/4;
        for (int i = b*256 + threadIdx.x; i < n4; i += 512*256) {
            float4 v = x[i];
            m = fmaxf(m, fmaxf(fmaxf(fabsf(v.x), fabsf(v.y)), fmaxf(fabsf(v.z), fabsf(v.w))));
        }
    } else {
        const float* w = (b == 513) ? w2 : w1;
        for (int i = threadIdx.x; i < 36864; i += 256) m = fmaxf(m, fabsf(w[i]));
    }
    #pragma unroll
    for (int o = 16; o; o >>= 1) m = fmaxf(m, __shfl_xor_sync(0xffffffffu, m, o));
    __shared__ float sm[8];
    if ((threadIdx.x & 31) == 0) sm[threadIdx.x >> 5] = m;
    __syncthreads();
    if (threadIdx.x == 0) {
        float mm = sm[0];
        #pragma unroll
        for (int i = 1; i < 8; i++) mm = fmaxf(mm, sm[i]);
        if (b < 512) g_part[b] = mm;
        else if (b == 512) g_maxw1 = mm;
        else g_maxw2 = mm;
    }
}

// ---------------- prep: final max|x| (block 36) + weight quant/wsum (0..35) ---
__global__ void __launch_bounds__(256) prepKernel(const float* __restrict__ w1,
                                                  const float* __restrict__ w2) {
    cudaGridDependencySynchronize();
    const unsigned M = 0x01010101u;
    if (blockIdx.x == 36) {
        float m = fmaxf(g_part[threadIdx.x], g_part[threadIdx.x + 256]);
        #pragma unroll
        for (int o = 16; o; o >>= 1) m = fmaxf(m, __shfl_xor_sync(0xffffffffu, m, o));
        __shared__ float sm[8];
        if ((threadIdx.x & 31) == 0) sm[threadIdx.x >> 5] = m;
        __syncthreads();
        if (threadIdx.x == 0) {
            float mm = sm[0];
            #pragma unroll
            for (int i = 1; i < 8; i++) mm = fmaxf(mm, sm[i]);
            g_maxabs_x = mm;
        }
        return;
    }
    // weight quant + wsum: warp handles item (sel, c4, pos)
    int item = blockIdx.x*8 + (threadIdx.x >> 5);
    int lane = threadIdx.x & 31;
    int sel = item / 144;
    int g   = item - sel*144;
    int c4  = g / 9, pos = g - c4*9;
    const float* w = sel ? w2 : w1;
    float s = (sel ? g_maxw2 : g_maxw1) * (1.0f/127.0f);
    unsigned* wpout = sel ? g_qw2p : g_qw1p;
    unsigned wds[2];
    #pragma unroll
    for (int h = 0; h < 2; h++) {
        int o = lane + 32*h;
        unsigned word = 0;
        #pragma unroll
        for (int j = 0; j < 4; j++) {
            float q = rintf(w[o*576 + (c4*4 + j)*9 + pos] / s);
            q = fminf(127.f, fmaxf(-127.f, q));
            word |= (((unsigned)(int)q) & 0xffu) << (8*j);
        }
        wpout[c4*576 + pos*64 + o] = word;
        wds[h] = word;
    }
    unsigned acc[8];
    #pragma unroll
    for (int k = 0; k < 8; k++) {
        unsigned v = ((wds[0] >> k) & M) + ((wds[1] >> k) & M);
        #pragma unroll
        for (int of = 16; of; of >>= 1) v += __shfl_xor_sync(0xffffffffu, v, of);
        acc[k] = v;
    }
    int j = lane >> 3, k = lane & 7;
    int* wsum = sel ? g_wsum2 : g_wsum1;
    wsum[((c4*4 + j)*8 + k)*9 + pos] = (int)((acc[k] >> (8*j)) & 0xffu);
}

// ---------------- fused quantize + bit-stats + int8 DP4A conv + BN (+identity) ----
// PASS 1: quantize x -> smem tile (+ write owned rows to g_qxp, stats1), conv, bn1 -> g_t1, max -> g_max_r1
// PASS 2: quantize g_t1 (relu) -> smem tile (+ stats2), conv, bn2 + identity -> dOut, max -> g_max_r2
template<int PASS>
__global__ void __launch_bounds__(128, 3) convKernel(
    const float* __restrict__ xsrc,
    const float* __restrict__ gamma, const float* __restrict__ beta,
    const float* __restrict__ mean,  const float* __restrict__ var,
    float* __restrict__ dOut)
{
    cudaGridDependencySynchronize();
    const uint4* __restrict__ wP = (const uint4*)((PASS == 1) ? g_qw1p : g_qw2p);
    const unsigned M = 0x01010101u;
    int n  = blockIdx.x / 28;
    int r0 = (blockIdx.x - n*28) * 2;

    __shared__ unsigned sIn[16*232];   // [c4][rows r0-1..r0+2][58 cols, -1 halo]
    __shared__ unsigned sA[128], sC0[128], sC55[128], sR[128];
    if (threadIdx.x < 128) {
        sC0[threadIdx.x] = 0; sC55[threadIdx.x] = 0; sR[threadIdx.x] = 0;
    }
    __syncthreads();

    float s = (PASS == 1) ? g_maxabs_x * (1.f/127.f) : g_max_r1 * (1.f/255.f);
    float sinv = 1.0f / s;

    const float* srcB = (PASS == 1) ? xsrc : (const float*)g_t1;
    int tg = threadIdx.x >> 3;          // c4 group 0..15
    int tl = threadIdx.x & 7;
    const float* cbase = srcB + (size_t)(n*CC + tg*4)*HW;
    bool rowB = (r0 == 0) || (r0 == 54);
    int  rrB  = (r0 == 0) ? 1 : 2;      // rr of the owned global border row
    int* stats = (PASS == 1) ? g_stats1 : g_stats2;

    unsigned aAll[8] = {0,0,0,0,0,0,0,0};
    for (int w = tl; w < 232; w += 8) {
        int rr = w / 58, cc = w - rr*58;
        int gr = r0 - 1 + rr, gc = cc - 1;
        unsigned word = 0;
        if ((unsigned)gr < 56u && (unsigned)gc < 56u) {
            int hw = gr*WID + gc;
            #pragma unroll
            for (int j = 0; j < 4; j++) {
                float v = cbase[j*HW + hw];
                float q;
                if (PASS == 1) q = fminf(127.f, fmaxf(-127.f, rintf(v * sinv)));
                else           q = fminf(255.f, rintf(fmaxf(v, 0.f) * sinv));
                word |= (((unsigned)(int)q) & 0xffu) << (8*j);
            }
            if (rr == 1 || rr == 2) {   // owned row (each global row owned by 1 block)
                if (PASS == 1) g_qxp[(n*16 + tg)*HW + hw] = word;
                #pragma unroll
                for (int k = 0; k < 8; k++) aAll[k] += (word >> k) & M;
                if (cc == 1 || cc == 56) {
                    unsigned* arr = (cc == 1) ? sC0 : sC55;
                    #pragma unroll
                    for (int k = 0; k < 8; k++) atomicAdd(&arr[tg*8 + k], (word >> k) & M);
                }
                if (rowB && rr == rrB) {
                    #pragma unroll
                    for (int k = 0; k < 8; k++) atomicAdd(&sR[tg*8 + k], (word >> k) & M);
                    if (cc == 1 || cc == 56) {
                        int corner = ((r0 == 54) ? 2 : 0) + (cc == 56);
                        #pragma unroll
                        for (int l = 0; l < 32; l++)
                            if ((word >> l) & 1)
                                atomicAdd(&stats[(5 + corner)*512 + (tg*4 + (l >> 3))*8 + (l & 7)], 1);
                    }
                }
            }
        }
        sIn[tg*232 + w] = word;
    }
    // sum aAll over the 8-lane subgroup (byte lanes <= 112, exact)
    #pragma unroll
    for (int k = 0; k < 8; k++) {
        #pragma unroll
        for (int o = 4; o; o >>= 1) aAll[k] += __shfl_xor_sync(0xffffffffu, aAll[k], o);
    }
    if (tl == 0) {
        #pragma unroll
        for (int k = 0; k < 8; k++) sA[tg*8 + k] = aAll[k];
    }
    __syncthreads();

    // push stats (fire-and-forget REDs; overlap with mainloop)
    if (threadIdx.x < 128) {
        int c4 = threadIdx.x >> 3, k = threadIdx.x & 7;
        unsigned vA = sA[threadIdx.x], v0 = sC0[threadIdx.x], v5 = sC55[threadIdx.x];
        unsigned vR = sR[threadIdx.x];
        int rreg = (r0 == 0) ? 1 : 2;
        #pragma unroll
        for (int j = 0; j < 4; j++) {
            int cb = (c4*4 + j)*8 + k;
            atomicAdd(&stats[cb], (int)((vA >> (8*j)) & 0xffu));
            unsigned b0 = (v0 >> (8*j)) & 0xffu; if (b0) atomicAdd(&stats[3*512 + cb], (int)b0);
            unsigned b5 = (v5 >> (8*j)) & 0xffu; if (b5) atomicAdd(&stats[4*512 + cb], (int)b5);
            if (rowB) {
                unsigned bR = (vR >> (8*j)) & 0xffu;
                if (bR) atomicAdd(&stats[rreg*512 + cb], (int)bR);
            }
        }
    }

    int ot    = threadIdx.x >> 3;       // 0..15
    int cbaseO = (threadIdx.x & 7) * 7; // 0..49

    int acc[2][4][7];
    #pragma unroll
    for (int lr = 0; lr < 2; lr++)
        #pragma unroll
        for (int j = 0; j < 4; j++)
            #pragma unroll
            for (int p = 0; p < 7; p++) acc[lr][j][p] = 0;

    const unsigned* sp = sIn + cbaseO;
    #pragma unroll 1
    for (int c4 = 0; c4 < 16; c4++) {
        const uint4* wpc = wP + c4*144 + ot;
        uint4 wv[9];
        #pragma unroll
        for (int q = 0; q < 9; q++) wv[q] = __ldg(wpc + q*16);
        const unsigned* spc = sp + c4*232;
        #pragma unroll
        for (int ir = 0; ir < 4; ir++) {
            unsigned iv[9];
            #pragma unroll
            for (int dc = 0; dc < 9; dc++) iv[dc] = spc[ir*58 + dc];
            if (ir < 3) {
                #pragma unroll
                for (int tt = 0; tt < 3; tt++) {
                    uint4 w4 = wv[ir*3 + tt];
                    unsigned wc[4] = {w4.x, w4.y, w4.z, w4.w};
                    #pragma unroll
                    for (int px = 0; px < 7; px++) {
                        unsigned a = iv[px + tt];
                        #pragma unroll
                        for (int j = 0; j < 4; j++)
                            acc[0][j][px] = DP<PASS>(a, wc[j], acc[0][j][px]);
                    }
                }
            }
            if (ir >= 1) {
                #pragma unroll
                for (int tt = 0; tt < 3; tt++) {
                    uint4 w4 = wv[(ir-1)*3 + tt];
                    unsigned wc[4] = {w4.x, w4.y, w4.z, w4.w};
                    #pragma unroll
                    for (int px = 0; px < 7; px++) {
                        unsigned a = iv[px + tt];
                        #pragma unroll
                        for (int j = 0; j < 4; j++)
                            acc[1][j][px] = DP<PASS>(a, wc[j], acc[1][j][px]);
                    }
                }
            }
        }
    }

    float sp1, sx = 0.f;
    if (PASS == 1) {
        sp1 = (g_maxabs_x * (1.f/127.f)) * (g_maxw1 * (1.f/127.f));
    } else {
        sp1 = (g_max_r1 * (1.f/255.f)) * (g_maxw2 * (1.f/127.f));
        sx  = g_maxabs_x * (1.f/127.f);
    }
    float A[4], B[4];
    #pragma unroll
    for (int j = 0; j < 4; j++) {
        int o = ot*4 + j;
        float inv = gamma[o] / sqrtf(var[o] + 1e-5f);
        A[j] = sp1 * inv;
        B[j] = beta[o] - mean[o]*inv;
    }

    float* dstp = (PASS == 1) ? g_t1 : dOut;
    float mx = 0.f;
    #pragma unroll
    for (int lr = 0; lr < 2; lr++) {
        int hwb = (r0 + lr)*WID + cbaseO;
        #pragma unroll
        for (int px = 0; px < 7; px++) {
            int hw = hwb + px;
            unsigned idw = 0;
            if (PASS == 2) idw = g_qxp[(n*16 + ot)*HW + hw];
            #pragma unroll
            for (int j = 0; j < 4; j++) {
                float t = (float)acc[lr][j][px] * A[j] + B[j];
                if (PASS == 2) {
                    int qb = (int)((int8_t)((idw >> (8*j)) & 0xffu));
                    t += (float)qb * sx;
                }
                dstp[(n*CC + ot*4 + j)*HW + hw] = t;
                mx = fmaxf(mx, t);
            }
        }
    }
    #pragma unroll
    for (int o = 16; o; o >>= 1) mx = fmaxf(mx, __shfl_xor_sync(0xffffffffu, mx, o));
    __shared__ float smx[4];
    if ((threadIdx.x & 31) == 0) smx[threadIdx.x >> 5] = mx;
    __syncthreads();
    if (threadIdx.x == 0) {
        float m = fmaxf(fmaxf(smx[0], smx[1]), fmaxf(smx[2], smx[3]));
        atomicMaxF((PASS == 1) ? &g_max_r1 : &g_max_r2, m);
    }
}

// ---------------- HM_act / HM_energy from factorized stats ----------------
__device__ __forceinline__ long long energyFor(const int* stats, const int* wsum, int cb) {
    int S   = stats[        cb];
    int r0  = stats[ 512  + cb];
    int r55 = stats[1024  + cb];
    int c0  = stats[1536  + cb];
    int c55 = stats[2048  + cb];
    int s00 = stats[2560  + cb];
    int s0b = stats[3072  + cb];
    int sb0 = stats[3584  + cb];
    int sbb = stats[4096  + cb];
    long long en = 0;
    #pragma unroll
    for (int kh = 0; kh < 3; kh++) {
        #pragma unroll
        for (int kw = 0; kw < 3; kw++) {
            int xs = S;
            if (kh == 2) xs -= r0;  else if (kh == 0) xs -= r55;
            if (kw == 2) xs -= c0;  else if (kw == 0) xs -= c55;
            if (kh == 2 && kw == 2) xs += s00;
            if (kh == 2 && kw == 0) xs += s0b;
            if (kh == 0 && kw == 2) xs += sb0;
            if (kh == 0 && kw == 0) xs += sbb;
            en += (long long)wsum[cb*9 + kh*3 + kw] * (long long)xs;
        }
    }
    return en;
}

// ---------------- final QuantReLU on d_out (in place) + finalize (block 784) --
__global__ void __launch_bounds__(256) finalQuantFin(float* __restrict__ out) {
    cudaGridDependencySynchronize();
    if (blockIdx.x == 784) {
        int t = threadIdx.x;
        long long act = 0, en = 0;
        for (int cb = t; cb < 512; cb += 256) {
            act += (long long)g_stats1[cb] + (long long)g_stats2[cb];
            en  += energyFor(g_stats1, g_wsum1, cb) + energyFor(g_stats2, g_wsum2, cb);
        }
        __shared__ long long sa[256], se[256];
        sa[t] = act; se[t] = en;
        __syncthreads();
        for (int step = 128; step; step >>= 1) {
            if (t < step) { sa[t] += sa[t + step]; se[t] += se[t + step]; }
            __syncthreads();
        }
        if (t == 0) {
            out[NN*CC*HW    ] = (float)sa[0];   // HM_act
            out[NN*CC*HW + 1] = (float)se[0];   // HM_energy
        }
        return;
    }
    float s = g_max_r2 * (1.f/255.f);
    float sinv = 1.0f / s;
    float4* o4 = (float4*)out;
    int base = blockIdx.x*256 + threadIdx.x;
    #pragma unroll
    for (int it = 0; it < 4; it++) {
        int i = base + it*200704;
        float4 v = o4[i];
        v.x = fminf(255.f, rintf(fmaxf(v.x, 0.f) * sinv)) * s;
        v.y = fminf(255.f, rintf(fmaxf(v.y, 0.f) * sinv)) * s;
        v.z = fminf(255.f, rintf(fmaxf(v.z, 0.f) * sinv)) * s;
        v.w = fminf(255.f, rintf(fmaxf(v.w, 0.f) * sinv)) * s;
        o4[i] = v;
    }
}

// ---------------- PDL launch helper ----------------
template <typename F, typename... Args>
static inline void launchPDL(F f, unsigned grid, unsigned block, Args... args) {
    cudaLaunchConfig_t cfg = {};
    cfg.gridDim  = dim3(grid, 1, 1);
    cfg.blockDim = dim3(block, 1, 1);
    cudaLaunchAttribute at[1];
    at[0].id = cudaLaunchAttributeProgrammaticStreamSerialization;
    at[0].val.programmaticStreamSerializationAllowed = 1;
    cfg.attrs = at;
    cfg.numAttrs = 1;
    cfg.stream = 0;
    cudaLaunchKernelEx(&cfg, f, args...);
}

// ---------------- launch ----------------
extern "C" void kernel_launch(void* const* d_in, const int* in_sizes, int n_in,
                              void* d_out, int out_size) {
    const float* x  = (const float*)d_in[0];
    const float* w1 = (const float*)d_in[1];
    const float* w2 = (const float*)d_in[2];
    const float* g1 = (const float*)d_in[3];
    const float* b1 = (const float*)d_in[4];
    const float* m1 = (const float*)d_in[5];
    const float* v1 = (const float*)d_in[6];
    const float* g2 = (const float*)d_in[7];
    const float* b2 = (const float*)d_in[8];
    const float* m2 = (const float*)d_in[9];
    const float* v2 = (const float*)d_in[10];
    float* out = (float*)d_out;

    reduceA<<<515, 256>>>((const float4*)x, w1, w2);
    launchPDL(prepKernel, 37, 256, w1, w2);
    launchPDL(convKernel<1>, 448, 128, x, g1, b1, m1, v1, (float*)nullptr);
    launchPDL(convKernel<2>, 448, 128, (const float*)nullptr, g2, b2, m2, v2, out);
    launchPDL(finalQuantFin, 785, 256, out);
}

// round 10
// speedup vs baseline: 1.1030x; 1.1030x over previous
#include <cuda_runtime.h>
#include <cstdint>

// ---------------- problem constants ----------------
#define NN 16
#define CC 64
#define HW 3136       // 56*56
#define WID 56

// ---------------- device scratch ----------------
__device__ float g_maxabs_x, g_maxw1, g_maxw2, g_max_r1, g_max_r2;
__device__ float g_part[512];
__device__ unsigned g_qxp[NN*16*HW];     // packed int8 qx: (n, c4, hw), byte j = channel 4*c4+j
__device__ unsigned g_q1p[NN*16*HW];     // packed uint8 q1
__device__ float    g_t1 [NN*CC*HW];     // bn1 output (pre-relu), fp32
__device__ unsigned g_qw1p[9216];        // packed weights: [c4][pos][o]
__device__ unsigned g_qw2p[9216];
__device__ int g_wsum1[4608], g_wsum2[4608];     // [cb][pos], cb = c*8+bit
__device__ int g_stats1[9*512], g_stats2[9*512]; // 9 stats x 512 channel-bits

__device__ __forceinline__ void atomicMaxF(float* a, float v) {
    atomicMax((int*)a, __float_as_int(v));   // valid for non-negative floats
}
// warp max of non-negative floats via order-preserving unsigned bits
__device__ __forceinline__ float warpMaxPos(float v) {
    return __uint_as_float(__reduce_max_sync(0xffffffffu, __float_as_uint(v)));
}
__device__ __forceinline__ int dp4a_ss(unsigned a, unsigned b, int c) {
    int r; asm("dp4a.s32.s32 %0, %1, %2, %3;" : "=r"(r) : "r"(a), "r"(b), "r"(c)); return r;
}
__device__ __forceinline__ int dp4a_us(unsigned a, unsigned b, int c) {
    int r; asm("dp4a.u32.s32 %0, %1, %2, %3;" : "=r"(r) : "r"(a), "r"(b), "r"(c)); return r;
}
template<int PASS>
__device__ __forceinline__ int DP(unsigned a, unsigned b, int c) {
    return (PASS == 1) ? dp4a_ss(a, b, c) : dp4a_us(a, b, c);
}

// ---------------- reduceA: partial max|x| (0..511), max|w| (512,513), init (514)
__global__ void reduceA(const float4* __restrict__ x,
                        const float* __restrict__ w1, const float* __restrict__ w2) {
    int b = blockIdx.x;
    if (b == 514) {
        if (threadIdx.x == 0) { g_max_r1 = 0.f; g_max_r2 = 0.f; }
        for (int i = threadIdx.x; i < 4608; i += 256) { g_stats1[i] = 0; g_stats2[i] = 0; }
        return;
    }
    float m = 0.f;
    if (b < 512) {
        const int n4 = NN*CC*HW/4;
        for (int i = b*256 + threadIdx.x; i < n4; i += 512*256) {
            float4 v = x[i];
            m = fmaxf(m, fmaxf(fmaxf(fabsf(v.x), fabsf(v.y)), fmaxf(fabsf(v.z), fabsf(v.w))));
        }
    } else {
        const float* w = (b == 513) ? w2 : w1;
        for (int i = threadIdx.x; i < 36864; i += 256) m = fmaxf(m, fabsf(w[i]));
    }
    m = warpMaxPos(m);
    __shared__ float sm[8];
    if ((threadIdx.x & 31) == 0) sm[threadIdx.x >> 5] = m;
    __syncthreads();
    if (threadIdx.x == 0) {
        float mm = sm[0];
        #pragma unroll
        for (int i = 1; i < 8; i++) mm = fmaxf(mm, sm[i]);
        if (b < 512) g_part[b] = mm;
        else if (b == 512) g_maxw1 = mm;
        else g_maxw2 = mm;
    }
}

// ---------------- fused quantize + bit stats (+ weight wsum blocks on PASS 1) --
// Data blocks 0..511: (n, c4, half); each handles 392 words (28 rows x 14).
// Main loop counts ONLY aAll; borders recomputed by dedicated warps (0..2).
// PASS 1 extra blocks 512..547: weight quant + pack + wsum (one warp per item).
template<int PASS>
__global__ void __launch_bounds__(256) quantStatsKernel(const float* __restrict__ xin,
                                                        const float* __restrict__ w1,
                                                        const float* __restrict__ w2) {
    cudaGridDependencySynchronize();
    const unsigned M = 0x01010101u;
    if (PASS == 1 && blockIdx.x >= 512) {
        // ---- weight quant + wsum: warp handles item (sel, c4, pos) ----
        int item = (blockIdx.x - 512)*8 + (threadIdx.x >> 5);
        int lane = threadIdx.x & 31;
        int sel = item / 144;
        int g   = item - sel*144;
        int c4  = g / 9, pos = g - c4*9;
        const float* w = sel ? w2 : w1;
        float s = (sel ? g_maxw2 : g_maxw1) * (1.0f/127.0f);
        unsigned* wpout = sel ? g_qw2p : g_qw1p;
        unsigned wds[2];
        #pragma unroll
        for (int h = 0; h < 2; h++) {
            int o = lane + 32*h;
            unsigned word = 0;
            #pragma unroll
            for (int j = 0; j < 4; j++) {
                float q = rintf(w[o*576 + (c4*4 + j)*9 + pos] / s);
                q = fminf(127.f, fmaxf(-127.f, q));
                word |= (((unsigned)(int)q) & 0xffu) << (8*j);
            }
            wpout[c4*576 + pos*64 + o] = word;
            wds[h] = word;
        }
        unsigned acc[8];
        #pragma unroll
        for (int k = 0; k < 8; k++)
            acc[k] = __reduce_add_sync(0xffffffffu, ((wds[0] >> k) & M) + ((wds[1] >> k) & M));
        int j = lane >> 3, k = lane & 7;
        int* wsum = sel ? g_wsum2 : g_wsum1;
        wsum[((c4*4 + j)*8 + k)*9 + pos] = (int)((acc[k] >> (8*j)) & 0xffu);
        return;
    }

    int n    = blockIdx.x >> 5;         // 0..15
    int rem  = blockIdx.x & 31;
    int c4   = rem >> 1;                // 0..15
    int half = rem & 1;                 // 0..1
    const float* src = (PASS == 1) ? xin : (const float*)g_t1;
    const float4* s0 = (const float4*)(src + (size_t)(n*CC + c4*4)*HW);
    unsigned* qp = (PASS == 1) ? g_qxp : g_q1p;
    uint4* dst = (uint4*)(qp + (size_t)(n*16 + c4)*HW);

    __shared__ unsigned scCor[128];   // 4 corners x 32 (j*8+k)
    __shared__ unsigned ws[8*48];     // 8 warps x [aAll_lo(8), aAll_hi(8), R0(8), R55(8), C0(8), C55(8)]
    __shared__ float sMaxW[8];

    if (PASS == 1) {
        float mloc = 0.f;
        for (int i = threadIdx.x; i < 512; i += 256) mloc = fmaxf(mloc, g_part[i]);
        mloc = warpMaxPos(mloc);
        if ((threadIdx.x & 31) == 0) sMaxW[threadIdx.x >> 5] = mloc;
    }
    if (threadIdx.x < 128) scCor[threadIdx.x] = 0;
    __syncthreads();

    float s;
    if (PASS == 1) {
        float mm = sMaxW[0];
        #pragma unroll
        for (int i = 1; i < 8; i++) mm = fmaxf(mm, sMaxW[i]);
        if (blockIdx.x == 0 && threadIdx.x == 0) g_maxabs_x = mm;
        s = mm * (1.0f/127.0f);
    } else {
        s = g_max_r1 * (1.0f/255.0f);
    }
    float sinv = 1.0f / s;

    // quantize the word-quad at index i (hw = 4i..4i+3, 4 channels packed per word)
    auto quantQuad = [&](int i, unsigned w[4]) {
        float4 f0 = s0[i];
        float4 f1 = s0[784 + i];
        float4 f2 = s0[1568 + i];
        float4 f3 = s0[2352 + i];
        float q0[4], q1v[4], q2[4], q3[4];
        #pragma unroll
        for (int j = 0; j < 4; j++) {
            float vx = (j==0)?f0.x:(j==1)?f1.x:(j==2)?f2.x:f3.x;
            float vy = (j==0)?f0.y:(j==1)?f1.y:(j==2)?f2.y:f3.y;
            float vz = (j==0)?f0.z:(j==1)?f1.z:(j==2)?f2.z:f3.z;
            float vw = (j==0)?f0.w:(j==1)?f1.w:(j==2)?f2.w:f3.w;
            if (PASS == 1) {
                q0[j]  = fminf(127.f, fmaxf(-127.f, rintf(vx * sinv)));
                q1v[j] = fminf(127.f, fmaxf(-127.f, rintf(vy * sinv)));
                q2[j]  = fminf(127.f, fmaxf(-127.f, rintf(vz * sinv)));
                q3[j]  = fminf(127.f, fmaxf(-127.f, rintf(vw * sinv)));
            } else {
                q0[j]  = fminf(255.f, rintf(fmaxf(vx, 0.f) * sinv));
                q1v[j] = fminf(255.f, rintf(fmaxf(vy, 0.f) * sinv));
                q2[j]  = fminf(255.f, rintf(fmaxf(vz, 0.f) * sinv));
                q3[j]  = fminf(255.f, rintf(fmaxf(vw, 0.f) * sinv));
            }
        }
        w[0] = w[1] = w[2] = w[3] = 0;
        #pragma unroll
        for (int j = 0; j < 4; j++) {
            w[0] |= (((unsigned)(int)q0[j])  & 0xffu) << (8*j);
            w[1] |= (((unsigned)(int)q1v[j]) & 0xffu) << (8*j);
            w[2] |= (((unsigned)(int)q2[j])  & 0xffu) << (8*j);
            w[3] |= (((unsigned)(int)q3[j])  & 0xffu) << (8*j);
        }
    };

    // -------- main loop: quantize + store + aAll only --------
    unsigned aAll[8] = {0,0,0,0,0,0,0,0};
    int ibase = half * 392;
    for (int li = threadIdx.x; li < 392; li += 256) {
        int i = ibase + li;
        unsigned w[4];
        quantQuad(i, w);
        dst[i] = make_uint4(w[0], w[1], w[2], w[3]);
        #pragma unroll
        for (int k = 0; k < 8; k++)
            aAll[k] += ((w[0]>>k)&M) + ((w[1]>>k)&M) + ((w[2]>>k)&M) + ((w[3]>>k)&M);
    }

    // -------- borders: warp 0 = row border, warp 1 = col 0, warp 2 = col 55 ---
    unsigned aB[8] = {0,0,0,0,0,0,0,0};
    int warp = threadIdx.x >> 5;
    int lane = threadIdx.x & 31;
    if (warp == 0 && lane < 14) {
        int i = half ? 770 + lane : lane;
        unsigned w[4];
        quantQuad(i, w);
        #pragma unroll
        for (int k = 0; k < 8; k++)
            aB[k] += ((w[0]>>k)&M) + ((w[1]>>k)&M) + ((w[2]>>k)&M) + ((w[3]>>k)&M);
        if (lane == 0) {
            int corner = half ? 2 : 0;  unsigned u = w[0];
            #pragma unroll
            for (int l = 0; l < 32; l++) atomicAdd(&scCor[corner*32 + l], (u >> l) & 1u);
        }
        if (lane == 13) {
            int corner = half ? 3 : 1;  unsigned u = w[3];
            #pragma unroll
            for (int l = 0; l < 32; l++) atomicAdd(&scCor[corner*32 + l], (u >> l) & 1u);
        }
    } else if (warp == 1 && lane < 28) {
        int i = ibase + lane*14;        // column 0 word (hw%56 == 0..3 -> w[0])
        unsigned w[4];
        quantQuad(i, w);
        #pragma unroll
        for (int k = 0; k < 8; k++) aB[k] += (w[0] >> k) & M;
    } else if (warp == 2 && lane < 28) {
        int i = ibase + lane*14 + 13;   // column 55 word -> w[3]
        unsigned w[4];
        quantQuad(i, w);
        #pragma unroll
        for (int k = 0; k < 8; k++) aB[k] += (w[3] >> k) & M;
    }

    // split aAll to 16-bit lanes (warp-sum of byte lanes can reach 256) + REDUX
    unsigned aLo[8], aHi[8];
    #pragma unroll
    for (int k = 0; k < 8; k++) {
        aLo[k] = __reduce_add_sync(0xffffffffu, aAll[k] & 0x00FF00FFu);
        aHi[k] = __reduce_add_sync(0xffffffffu, (aAll[k] >> 8) & 0x00FF00FFu);
        aB [k] = __reduce_add_sync(0xffffffffu, aB[k]);
    }
    if (lane == 0) {
        #pragma unroll
        for (int k = 0; k < 8; k++) {
            ws[warp*48 +     k] = aLo[k];
            ws[warp*48 + 8 + k] = aHi[k];
        }
        #pragma unroll
        for (int slot = 0; slot < 4; slot++)
            #pragma unroll
            for (int k = 0; k < 8; k++) ws[warp*48 + 16 + slot*8 + k] = 0;
        int region = (warp == 0) ? (half ? 2 : 1) : (warp == 1) ? 3 : (warp == 2) ? 4 : 0;
        if (region) {
            #pragma unroll
            for (int k = 0; k < 8; k++) ws[warp*48 + 16 + (region-1)*8 + k] = aB[k];
        }
    }
    __syncthreads();

    int* stats = (PASS == 1) ? g_stats1 : g_stats2;
    if (threadIdx.x < 8) {
        int k = threadIdx.x;
        unsigned vlo = 0, vhi = 0;
        #pragma unroll
        for (int wp = 0; wp < 8; wp++) {
            vlo += ws[wp*48 +     k];
            vhi += ws[wp*48 + 8 + k];
        }
        atomicAdd(&stats[(c4*4 + 0)*8 + k], (int)(vlo & 0xffffu));
        atomicAdd(&stats[(c4*4 + 2)*8 + k], (int)(vlo >> 16));
        atomicAdd(&stats[(c4*4 + 1)*8 + k], (int)(vhi & 0xffffu));
        atomicAdd(&stats[(c4*4 + 3)*8 + k], (int)(vhi >> 16));
    } else if (threadIdx.x < 40) {
        int t2   = threadIdx.x - 8;
        int sidx = 1 + (t2 >> 3);          // regions 1..4 (R0, R55, C0, C55)
        int k    = t2 & 7;
        unsigned v = 0;
        #pragma unroll
        for (int wp = 0; wp < 8; wp++) v += ws[wp*48 + 8 + sidx*8 + k];
        #pragma unroll
        for (int j = 0; j < 4; j++)
            atomicAdd(&stats[sidx*512 + (c4*4 + j)*8 + k], (int)((v >> (8*j)) & 0xffu));
    }
    if (threadIdx.x < 128) {
        int corner = threadIdx.x >> 5;
        int l = threadIdx.x & 31;
        int j = l >> 3, k = l & 7;
        int v = (int)scCor[threadIdx.x];
        if (v) atomicAdd(&stats[(5 + corner)*512 + (c4*4 + j)*8 + k], v);
    }
}

// ---------------- int8 DP4A conv + fused BN (+identity) + max-relu ----------------
template<int PASS>
__global__ void __launch_bounds__(128, 3) convKernel(
    const float* __restrict__ gamma, const float* __restrict__ beta,
    const float* __restrict__ mean,  const float* __restrict__ var,
    float* __restrict__ dOut)
{
    cudaGridDependencySynchronize();
    const unsigned* __restrict__ inP = (PASS == 1) ? g_qxp : g_q1p;
    const uint4* __restrict__ wP = (const uint4*)((PASS == 1) ? g_qw1p : g_qw2p);
    int n  = blockIdx.x / 28;
    int r0 = (blockIdx.x - n*28) * 2;

    __shared__ unsigned sIn[16*4*58];   // [c4][rows r0-1..r0+2][58 cols, -1 halo]
    for (int i = threadIdx.x; i < 16*4*58; i += 128) {
        int c4 = i / 232;
        int r2 = i - c4*232;
        int rr = r2 / 58;
        int cc = r2 - rr*58;
        int gr = r0 - 1 + rr, gc = cc - 1;
        unsigned v = 0;
        if ((unsigned)gr < 56u && (unsigned)gc < 56u)
            v = inP[(n*16 + c4)*HW + gr*WID + gc];
        sIn[i] = v;
    }
    __syncthreads();

    int ot    = threadIdx.x >> 3;       // 0..15
    int cbase = (threadIdx.x & 7) * 7;  // 0..49

    int acc[2][4][7];
    #pragma unroll
    for (int lr = 0; lr < 2; lr++)
        #pragma unroll
        for (int j = 0; j < 4; j++)
            #pragma unroll
            for (int p = 0; p < 7; p++) acc[lr][j][p] = 0;

    const unsigned* sp = sIn + cbase;
    #pragma unroll 1
    for (int c4 = 0; c4 < 16; c4++) {
        const uint4* wpc = wP + c4*144 + ot;
        uint4 wv[9];
        #pragma unroll
        for (int q = 0; q < 9; q++) wv[q] = __ldg(wpc + q*16);
        const unsigned* spc = sp + c4*232;
        #pragma unroll
        for (int ir = 0; ir < 4; ir++) {
            unsigned iv[9];
            #pragma unroll
            for (int dc = 0; dc < 9; dc++) iv[dc] = spc[ir*58 + dc];
            if (ir < 3) {
                #pragma unroll
                for (int tt = 0; tt < 3; tt++) {
                    uint4 w4 = wv[ir*3 + tt];
                    unsigned wc[4] = {w4.x, w4.y, w4.z, w4.w};
                    #pragma unroll
                    for (int px = 0; px < 7; px++) {
                        unsigned a = iv[px + tt];
                        #pragma unroll
                        for (int j = 0; j < 4; j++)
                            acc[0][j][px] = DP<PASS>(a, wc[j], acc[0][j][px]);
                    }
                }
            }
            if (ir >= 1) {
                #pragma unroll
                for (int tt = 0; tt < 3; tt++) {
                    uint4 w4 = wv[(ir-1)*3 + tt];
                    unsigned wc[4] = {w4.x, w4.y, w4.z, w4.w};
                    #pragma unroll
                    for (int px = 0; px < 7; px++) {
                        unsigned a = iv[px + tt];
                        #pragma unroll
                        for (int j = 0; j < 4; j++)
                            acc[1][j][px] = DP<PASS>(a, wc[j], acc[1][j][px]);
                    }
                }
            }
        }
    }

    float sp1, sx = 0.f;
    if (PASS == 1) {
        sp1 = (g_maxabs_x * (1.f/127.f)) * (g_maxw1 * (1.f/127.f));
    } else {
        sp1 = (g_max_r1 * (1.f/255.f)) * (g_maxw2 * (1.f/127.f));
        sx  = g_maxabs_x * (1.f/127.f);
    }
    float A[4], B[4];
    #pragma unroll
    for (int j = 0; j < 4; j++) {
        int o = ot*4 + j;
        float inv = gamma[o] / sqrtf(var[o] + 1e-5f);
        A[j] = sp1 * inv;
        B[j] = beta[o] - mean[o]*inv;
    }

    float* dstp = (PASS == 1) ? g_t1 : dOut;
    float mx = 0.f;
    #pragma unroll
    for (int lr = 0; lr < 2; lr++) {
        int hwb = (r0 + lr)*WID + cbase;
        #pragma unroll
        for (int px = 0; px < 7; px++) {
            int hw = hwb + px;
            unsigned idw = 0;
            if (PASS == 2) idw = g_qxp[(n*16 + ot)*HW + hw];
            #pragma unroll
            for (int j = 0; j < 4; j++) {
                float t = (float)acc[lr][j][px] * A[j] + B[j];
                if (PASS == 2) {
                    int qb = (int)((int8_t)((idw >> (8*j)) & 0xffu));
                    t += (float)qb * sx;
                }
                dstp[(n*CC + ot*4 + j)*HW + hw] = t;
                mx = fmaxf(mx, t);
            }
        }
    }
    mx = warpMaxPos(mx);
    __shared__ float smx[4];
    if ((threadIdx.x & 31) == 0) smx[threadIdx.x >> 5] = mx;
    __syncthreads();
    if (threadIdx.x == 0) {
        float m = fmaxf(fmaxf(smx[0], smx[1]), fmaxf(smx[2], smx[3]));
        atomicMaxF((PASS == 1) ? &g_max_r1 : &g_max_r2, m);
    }
}

// ---------------- HM_act / HM_energy from factorized stats ----------------
__device__ __forceinline__ long long energyFor(const int* stats, const int* wsum, int cb) {
    int S   = stats[        cb];
    int r0  = stats[ 512  + cb];
    int r55 = stats[1024  + cb];
    int c0  = stats[1536  + cb];
    int c55 = stats[2048  + cb];
    int s00 = stats[2560  + cb];
    int s0b = stats[3072  + cb];
    int sb0 = stats[3584  + cb];
    int sbb = stats[4096  + cb];
    long long en = 0;
    #pragma unroll
    for (int kh = 0; kh < 3; kh++) {
        #pragma unroll
        for (int kw = 0; kw < 3; kw++) {
            int xs = S;
            if (kh == 2) xs -= r0;  else if (kh == 0) xs -= r55;
            if (kw == 2) xs -= c0;  else if (kw == 0) xs -= c55;
            if (kh == 2 && kw == 2) xs += s00;
            if (kh == 2 && kw == 0) xs += s0b;
            if (kh == 0 && kw == 2) xs += sb0;
            if (kh == 0 && kw == 0) xs += sbb;
            en += (long long)wsum[cb*9 + kh*3 + kw] * (long long)xs;
        }
    }
    return en;
}

// ---------------- final QuantReLU on d_out (in place) + finalize (block 1568) --
__global__ void __launch_bounds__(256) finalQuantFin(float* __restrict__ out) {
    cudaGridDependencySynchronize();
    if (blockIdx.x == 1568) {
        int t = threadIdx.x;
        long long act = 0, en = 0;
        for (int cb = t; cb < 512; cb += 256) {
            act += (long long)g_stats1[cb] + (long long)g_stats2[cb];
            en  += energyFor(g_stats1, g_wsum1, cb) + energyFor(g_stats2, g_wsum2, cb);
        }
        __shared__ long long sa[256], se[256];
        sa[t] = act; se[t] = en;
        __syncthreads();
        for (int step = 128; step; step >>= 1) {
            if (t < step) { sa[t] += sa[t + step]; se[t] += se[t + step]; }
            __syncthreads();
        }
        if (t == 0) {
            out[NN*CC*HW    ] = (float)sa[0];   // HM_act
            out[NN*CC*HW + 1] = (float)se[0];   // HM_energy
        }
        return;
    }
    float s = g_max_r2 * (1.f/255.f);
    float sinv = 1.0f / s;
    float4* o4 = (float4*)out;
    int base = blockIdx.x*256 + threadIdx.x;
    #pragma unroll
    for (int it = 0; it < 2; it++) {
        int i = base + it*401408;
        float4 v = o4[i];
        v.x = fminf(255.f, rintf(fmaxf(v.x, 0.f) * sinv)) * s;
        v.y = fminf(255.f, rintf(fmaxf(v.y, 0.f) * sinv)) * s;
        v.z = fminf(255.f, rintf(fmaxf(v.z, 0.f) * sinv)) * s;
        v.w = fminf(255.f, rintf(fmaxf(v.w, 0.f) * sinv)) * s;
        o4[i] = v;
    }
}

// ---------------- PDL launch helper ----------------
template <typename F, typename... Args>
static inline void launchPDL(F f, unsigned grid, unsigned block, Args... args) {
    cudaLaunchConfig_t cfg = {};
    cfg.gridDim  = dim3(grid, 1, 1);
    cfg.blockDim = dim3(block, 1, 1);
    cudaLaunchAttribute at[1];
    at[0].id = cudaLaunchAttributeProgrammaticStreamSerialization;
    at[0].val.programmaticStreamSerializationAllowed = 1;
    cfg.attrs = at;
    cfg.numAttrs = 1;
    cfg.stream = 0;
    cudaLaunchKernelEx(&cfg, f, args...);
}

// ---------------- launch ----------------
extern "C" void kernel_launch(void* const* d_in, const int* in_sizes, int n_in,
                              void* d_out, int out_size) {
    const float* x  = (const float*)d_in[0];
    const float* w1 = (const float*)d_in[1];
    const float* w2 = (const float*)d_in[2];
    const float* g1 = (const float*)d_in[3];
    const float* b1 = (const float*)d_in[4];
    const float* m1 = (const float*)d_in[5];
    const float* v1 = (const float*)d_in[6];
    const float* g2 = (const float*)d_in[7];
    const float* b2 = (const float*)d_in[8];
    const float* m2 = (const float*)d_in[9];
    const float* v2 = (const float*)d_in[10];
    float* out = (float*)d_out;

    reduceA<<<515, 256>>>((const float4*)x, w1, w2);
    launchPDL(quantStatsKernel<1>, 548, 256, x, w1, w2);
    launchPDL(convKernel<1>, 448, 128, g1, b1, m1, v1, (float*)nullptr);
    launchPDL(quantStatsKernel<2>, 512, 256, (const float*)nullptr, (const float*)nullptr, (const float*)nullptr);
    launchPDL(convKernel<2>, 448, 128, g2, b2, m2, v2, out);
    launchPDL(finalQuantFin, 1569, 256, out);
}

// round 11
// speedup vs baseline: 1.1411x; 1.0346x over previous
#include <cuda_runtime.h>
#include <cstdint>

// ---------------- problem constants ----------------
#define NN 16
#define CC 64
#define HW 3136       // 56*56
#define WID 56

// ---------------- device scratch ----------------
__device__ float g_maxabs_x, g_maxw1, g_maxw2, g_max_r1, g_max_r2;
__device__ float g_part[512];
__device__ unsigned g_qxp[NN*16*HW];     // packed int8 qx: (n, c4, hw), byte j = channel 4*c4+j
__device__ unsigned g_q1p[NN*16*HW];     // packed uint8 q1
__device__ float    g_t1 [NN*CC*HW];     // bn1 output (pre-relu), fp32
__device__ unsigned g_qw1p[9216];        // packed weights: [c4][pos][o]
__device__ unsigned g_qw2p[9216];
__device__ int g_wsum1[4608], g_wsum2[4608];     // [cb][pos], cb = c*8+bit
__device__ int g_stats1[9*512], g_stats2[9*512]; // 9 stats x 512 channel-bits

__device__ __forceinline__ void atomicMaxF(float* a, float v) {
    atomicMax((int*)a, __float_as_int(v));   // valid for non-negative floats
}
__device__ __forceinline__ float warpMaxPos(float v) {
    return __uint_as_float(__reduce_max_sync(0xffffffffu, __float_as_uint(v)));
}

// int8 tensor-core mma: D(16x8,s32) += A(16x32) * B(32x8)
template<int PASS>
__device__ __forceinline__ void MMA8(int* c, unsigned a0, unsigned a1, unsigned a2, unsigned a3,
                                     unsigned b0, unsigned b1) {
    if (PASS == 1)
        asm volatile(
            "mma.sync.aligned.m16n8k32.row.col.s32.s8.s8.s32 "
            "{%0,%1,%2,%3},{%4,%5,%6,%7},{%8,%9},{%0,%1,%2,%3};"
            : "+r"(c[0]), "+r"(c[1]), "+r"(c[2]), "+r"(c[3])
            : "r"(a0), "r"(a1), "r"(a2), "r"(a3), "r"(b0), "r"(b1));
    else
        asm volatile(
            "mma.sync.aligned.m16n8k32.row.col.s32.u8.s8.s32 "
            "{%0,%1,%2,%3},{%4,%5,%6,%7},{%8,%9},{%0,%1,%2,%3};"
            : "+r"(c[0]), "+r"(c[1]), "+r"(c[2]), "+r"(c[3])
            : "r"(a0), "r"(a1), "r"(a2), "r"(a3), "r"(b0), "r"(b1));
}

// ---------------- reduceA: partial max|x| (0..511), max|w| (512,513), init (514)
__global__ void reduceA(const float4* __restrict__ x,
                        const float* __restrict__ w1, const float* __restrict__ w2) {
    int b = blockIdx.x;
    if (b == 514) {
        if (threadIdx.x == 0) { g_max_r1 = 0.f; g_max_r2 = 0.f; }
        for (int i = threadIdx.x; i < 4608; i += 256) { g_stats1[i] = 0; g_stats2[i] = 0; }
        return;
    }
    float m = 0.f;
    if (b < 512) {
        const int n4 = NN*CC*HW/4;
        for (int i = b*256 + threadIdx.x; i < n4; i += 512*256) {
            float4 v = x[i];
            m = fmaxf(m, fmaxf(fmaxf(fabsf(v.x), fabsf(v.y)), fmaxf(fabsf(v.z), fabsf(v.w))));
        }
    } else {
        const float* w = (b == 513) ? w2 : w1;
        for (int i = threadIdx.x; i < 36864; i += 256) m = fmaxf(m, fabsf(w[i]));
    }
    m = warpMaxPos(m);
    __shared__ float sm[8];
    if ((threadIdx.x & 31) == 0) sm[threadIdx.x >> 5] = m;
    __syncthreads();
    if (threadIdx.x == 0) {
        float mm = sm[0];
        #pragma unroll
        for (int i = 1; i < 8; i++) mm = fmaxf(mm, sm[i]);
        if (b < 512) g_part[b] = mm;
        else if (b == 512) g_maxw1 = mm;
        else g_maxw2 = mm;
    }
}

// ---------------- fused quantize + bit stats (+ weight wsum blocks on PASS 1) --
template<int PASS>
__global__ void __launch_bounds__(256) quantStatsKernel(const float* __restrict__ xin,
                                                        const float* __restrict__ w1,
                                                        const float* __restrict__ w2) {
    cudaGridDependencySynchronize();
    const unsigned M = 0x01010101u;
    if (PASS == 1 && blockIdx.x >= 512) {
        int item = (blockIdx.x - 512)*8 + (threadIdx.x >> 5);
        int lane = threadIdx.x & 31;
        int sel = item / 144;
        int g   = item - sel*144;
        int c4  = g / 9, pos = g - c4*9;
        const float* w = sel ? w2 : w1;
        float s = (sel ? g_maxw2 : g_maxw1) * (1.0f/127.0f);
        unsigned* wpout = sel ? g_qw2p : g_qw1p;
        unsigned wds[2];
        #pragma unroll
        for (int h = 0; h < 2; h++) {
            int o = lane + 32*h;
            unsigned word = 0;
            #pragma unroll
            for (int j = 0; j < 4; j++) {
                float q = rintf(w[o*576 + (c4*4 + j)*9 + pos] / s);
                q = fminf(127.f, fmaxf(-127.f, q));
                word |= (((unsigned)(int)q) & 0xffu) << (8*j);
            }
            wpout[c4*576 + pos*64 + o] = word;
            wds[h] = word;
        }
        unsigned acc[8];
        #pragma unroll
        for (int k = 0; k < 8; k++)
            acc[k] = __reduce_add_sync(0xffffffffu, ((wds[0] >> k) & M) + ((wds[1] >> k) & M));
        int j = lane >> 3, k = lane & 7;
        int* wsum = sel ? g_wsum2 : g_wsum1;
        wsum[((c4*4 + j)*8 + k)*9 + pos] = (int)((acc[k] >> (8*j)) & 0xffu);
        return;
    }

    int n    = blockIdx.x >> 5;
    int rem  = blockIdx.x & 31;
    int c4   = rem >> 1;
    int half = rem & 1;
    const float* src = (PASS == 1) ? xin : (const float*)g_t1;
    const float4* s0 = (const float4*)(src + (size_t)(n*CC + c4*4)*HW);
    unsigned* qp = (PASS == 1) ? g_qxp : g_q1p;
    uint4* dst = (uint4*)(qp + (size_t)(n*16 + c4)*HW);

    __shared__ unsigned scCor[128];
    __shared__ unsigned ws[8*48];
    __shared__ float sMaxW[8];

    if (PASS == 1) {
        float mloc = 0.f;
        for (int i = threadIdx.x; i < 512; i += 256) mloc = fmaxf(mloc, g_part[i]);
        mloc = warpMaxPos(mloc);
        if ((threadIdx.x & 31) == 0) sMaxW[threadIdx.x >> 5] = mloc;
    }
    if (threadIdx.x < 128) scCor[threadIdx.x] = 0;
    __syncthreads();

    float s;
    if (PASS == 1) {
        float mm = sMaxW[0];
        #pragma unroll
        for (int i = 1; i < 8; i++) mm = fmaxf(mm, sMaxW[i]);
        if (blockIdx.x == 0 && threadIdx.x == 0) g_maxabs_x = mm;
        s = mm * (1.0f/127.0f);
    } else {
        s = g_max_r1 * (1.0f/255.0f);
    }
    float sinv = 1.0f / s;

    auto quantQuad = [&](int i, unsigned w[4]) {
        float4 f0 = s0[i];
        float4 f1 = s0[784 + i];
        float4 f2 = s0[1568 + i];
        float4 f3 = s0[2352 + i];
        float q0[4], q1v[4], q2[4], q3[4];
        #pragma unroll
        for (int j = 0; j < 4; j++) {
            float vx = (j==0)?f0.x:(j==1)?f1.x:(j==2)?f2.x:f3.x;
            float vy = (j==0)?f0.y:(j==1)?f1.y:(j==2)?f2.y:f3.y;
            float vz = (j==0)?f0.z:(j==1)?f1.z:(j==2)?f2.z:f3.z;
            float vw = (j==0)?f0.w:(j==1)?f1.w:(j==2)?f2.w:f3.w;
            if (PASS == 1) {
                q0[j]  = fminf(127.f, fmaxf(-127.f, rintf(vx * sinv)));
                q1v[j] = fminf(127.f, fmaxf(-127.f, rintf(vy * sinv)));
                q2[j]  = fminf(127.f, fmaxf(-127.f, rintf(vz * sinv)));
                q3[j]  = fminf(127.f, fmaxf(-127.f, rintf(vw * sinv)));
            } else {
                q0[j]  = fminf(255.f, rintf(fmaxf(vx, 0.f) * sinv));
                q1v[j] = fminf(255.f, rintf(fmaxf(vy, 0.f) * sinv));
                q2[j]  = fminf(255.f, rintf(fmaxf(vz, 0.f) * sinv));
                q3[j]  = fminf(255.f, rintf(fmaxf(vw, 0.f) * sinv));
            }
        }
        w[0] = w[1] = w[2] = w[3] = 0;
        #pragma unroll
        for (int j = 0; j < 4; j++) {
            w[0] |= (((unsigned)(int)q0[j])  & 0xffu) << (8*j);
            w[1] |= (((unsigned)(int)q1v[j]) & 0xffu) << (8*j);
            w[2] |= (((unsigned)(int)q2[j])  & 0xffu) << (8*j);
            w[3] |= (((unsigned)(int)q3[j])  & 0xffu) << (8*j);
        }
    };

    unsigned aAll[8] = {0,0,0,0,0,0,0,0};
    int ibase = half * 392;
    for (int li = threadIdx.x; li < 392; li += 256) {
        int i = ibase + li;
        unsigned w[4];
        quantQuad(i, w);
        dst[i] = make_uint4(w[0], w[1], w[2], w[3]);
        #pragma unroll
        for (int k = 0; k < 8; k++)
            aAll[k] += ((w[0]>>k)&M) + ((w[1]>>k)&M) + ((w[2]>>k)&M) + ((w[3]>>k)&M);
    }

    unsigned aB[8] = {0,0,0,0,0,0,0,0};
    int warp = threadIdx.x >> 5;
    int lane = threadIdx.x & 31;
    if (warp == 0 && lane < 14) {
        int i = half ? 770 + lane : lane;
        unsigned w[4];
        quantQuad(i, w);
        #pragma unroll
        for (int k = 0; k < 8; k++)
            aB[k] += ((w[0]>>k)&M) + ((w[1]>>k)&M) + ((w[2]>>k)&M) + ((w[3]>>k)&M);
        if (lane == 0) {
            int corner = half ? 2 : 0;  unsigned u = w[0];
            #pragma unroll
            for (int l = 0; l < 32; l++) atomicAdd(&scCor[corner*32 + l], (u >> l) & 1u);
        }
        if (lane == 13) {
            int corner = half ? 3 : 1;  unsigned u = w[3];
            #pragma unroll
            for (int l = 0; l < 32; l++) atomicAdd(&scCor[corner*32 + l], (u >> l) & 1u);
        }
    } else if (warp == 1 && lane < 28) {
        int i = ibase + lane*14;
        unsigned w[4];
        quantQuad(i, w);
        #pragma unroll
        for (int k = 0; k < 8; k++) aB[k] += (w[0] >> k) & M;
    } else if (warp == 2 && lane < 28) {
        int i = ibase + lane*14 + 13;
        unsigned w[4];
        quantQuad(i, w);
        #pragma unroll
        for (int k = 0; k < 8; k++) aB[k] += (w[3] >> k) & M;
    }

    unsigned aLo[8], aHi[8];
    #pragma unroll
    for (int k = 0; k < 8; k++) {
        aLo[k] = __reduce_add_sync(0xffffffffu, aAll[k] & 0x00FF00FFu);
        aHi[k] = __reduce_add_sync(0xffffffffu, (aAll[k] >> 8) & 0x00FF00FFu);
        aB [k] = __reduce_add_sync(0xffffffffu, aB[k]);
    }
    if (lane == 0) {
        #pragma unroll
        for (int k = 0; k < 8; k++) {
            ws[warp*48 +     k] = aLo[k];
            ws[warp*48 + 8 + k] = aHi[k];
        }
        #pragma unroll
        for (int slot = 0; slot < 4; slot++)
            #pragma unroll
            for (int k = 0; k < 8; k++) ws[warp*48 + 16 + slot*8 + k] = 0;
        int region = (warp == 0) ? (half ? 2 : 1) : (warp == 1) ? 3 : (warp == 2) ? 4 : 0;
        if (region) {
            #pragma unroll
            for (int k = 0; k < 8; k++) ws[warp*48 + 16 + (region-1)*8 + k] = aB[k];
        }
    }
    __syncthreads();

    int* stats = (PASS == 1) ? g_stats1 : g_stats2;
    if (threadIdx.x < 8) {
        int k = threadIdx.x;
        unsigned vlo = 0, vhi = 0;
        #pragma unroll
        for (int wp = 0; wp < 8; wp++) {
            vlo += ws[wp*48 +     k];
            vhi += ws[wp*48 + 8 + k];
        }
        atomicAdd(&stats[(c4*4 + 0)*8 + k], (int)(vlo & 0xffffu));
        atomicAdd(&stats[(c4*4 + 2)*8 + k], (int)(vlo >> 16));
        atomicAdd(&stats[(c4*4 + 1)*8 + k], (int)(vhi & 0xffffu));
        atomicAdd(&stats[(c4*4 + 3)*8 + k], (int)(vhi >> 16));
    } else if (threadIdx.x < 40) {
        int t2   = threadIdx.x - 8;
        int sidx = 1 + (t2 >> 3);
        int k    = t2 & 7;
        unsigned v = 0;
        #pragma unroll
        for (int wp = 0; wp < 8; wp++) v += ws[wp*48 + 8 + sidx*8 + k];
        #pragma unroll
        for (int j = 0; j < 4; j++)
            atomicAdd(&stats[sidx*512 + (c4*4 + j)*8 + k], (int)((v >> (8*j)) & 0xffu));
    }
    if (threadIdx.x < 128) {
        int corner = threadIdx.x >> 5;
        int l = threadIdx.x & 31;
        int j = l >> 3, k = l & 7;
        int v = (int)scCor[threadIdx.x];
        if (v) atomicAdd(&stats[(5 + corner)*512 + (c4*4 + j)*8 + k], v);
    }
}

// ---------------- int8 TENSOR-CORE conv (mma.sync m16n8k32) + BN (+identity) ----
// Grid 448: block = (n, row-pair). 224 threads = 7 warps; warp w covers
// pixels (h0..h0+1, w*8..w*8+7), all 64 output channels (8 n-tiles).
// K = 576 processed as 2 channel-halves x 9 taps; per-half staging of
// input tile (8 c4 x 4 rows x 58 cols) and weights (8 c4 x 576, XOR-swizzled).
template<int PASS>
__global__ void __launch_bounds__(224) convKernel(
    const float* __restrict__ gamma, const float* __restrict__ beta,
    const float* __restrict__ mean,  const float* __restrict__ var,
    float* __restrict__ dOut)
{
    cudaGridDependencySynchronize();
    const unsigned* __restrict__ inP = (PASS == 1) ? g_qxp : g_q1p;
    const unsigned* __restrict__ wP  = (PASS == 1) ? g_qw1p : g_qw2p;
    int n  = blockIdx.x / 28;
    int h0 = (blockIdx.x - n*28) * 2;

    __shared__ unsigned sIn[8*232];     // [c4loc][rows h0-1..h0+2][58 cols, -1 halo]
    __shared__ unsigned sW [8*576];     // [c4loc][pos][o ^ ((c4loc&3)<<3)]
    __shared__ float sAc[64], sBc[64];
    __shared__ float smx[7];

    int tid  = threadIdx.x;
    int lane = tid & 31, wid = tid >> 5;
    int gid  = lane >> 2, t4 = lane & 3;
    int w0   = wid * 8;

    // BN coefficients (exact same expressions as before)
    float sp1, sx = 0.f;
    if (PASS == 1) {
        sp1 = (g_maxabs_x * (1.f/127.f)) * (g_maxw1 * (1.f/127.f));
    } else {
        sp1 = (g_max_r1 * (1.f/255.f)) * (g_maxw2 * (1.f/127.f));
        sx  = g_maxabs_x * (1.f/127.f);
    }
    if (tid < 64) {
        float inv = gamma[tid] / sqrtf(var[tid] + 1e-5f);
        sAc[tid] = sp1 * inv;
        sBc[tid] = beta[tid] - mean[tid]*inv;
    }

    int acc[8][4];
    #pragma unroll
    for (int nt = 0; nt < 8; nt++)
        #pragma unroll
        for (int r = 0; r < 4; r++) acc[nt][r] = 0;

    #pragma unroll 1
    for (int halfc = 0; halfc < 2; halfc++) {
        __syncthreads();   // protect previous phase (and BN smem on phase 0)
        // stage input tile for channels halfc*32 .. +31 (c4 = halfc*8 .. +7)
        for (int i = tid; i < 8*232; i += 224) {
            int c4l = i / 232;
            int r2 = i - c4l*232;
            int rr = r2 / 58, cc = r2 - rr*58;
            int gr = h0 - 1 + rr, gc = cc - 1;
            unsigned v = 0;
            if ((unsigned)gr < 56u && (unsigned)gc < 56u)
                v = inP[(n*16 + halfc*8 + c4l)*HW + gr*WID + gc];
            sIn[i] = v;
        }
        // stage weights, XOR-swizzled for conflict-free B-fragment loads
        for (int i = tid; i < 8*576; i += 224) {
            int c4l = i / 576;
            int r   = i - c4l*576;
            int pos = r >> 6, o = r & 63;
            sW[c4l*576 + (pos << 6) + (o ^ ((c4l & 3) << 3))] =
                wP[(halfc*8 + c4l)*576 + (pos << 6) + o];
        }
        __syncthreads();

        #pragma unroll
        for (int ph = 0; ph < 3; ph++) {
            #pragma unroll
            for (int pw = 0; pw < 3; pw++) {
                int pos = ph*3 + pw;
                int ccol = w0 + gid + pw;
                unsigned a0 = sIn[ t4     *232 +  ph   *58 + ccol];
                unsigned a1 = sIn[ t4     *232 + (ph+1)*58 + ccol];
                unsigned a2 = sIn[(4 + t4)*232 +  ph   *58 + ccol];
                unsigned a3 = sIn[(4 + t4)*232 + (ph+1)*58 + ccol];
                const unsigned* sWb0 = sW +  t4     *576 + pos*64;
                const unsigned* sWb1 = sW + (4 + t4)*576 + pos*64;
                unsigned sw8 = (unsigned)(t4 << 3);
                #pragma unroll
                for (int nt = 0; nt < 8; nt++) {
                    int o = nt*8 + gid;
                    unsigned b0 = sWb0[o ^ sw8];
                    unsigned b1 = sWb1[o ^ sw8];
                    MMA8<PASS>(acc[nt], a0, a1, a2, a3, b0, b1);
                }
            }
        }
    }

    // epilogue: BN (+identity), store, max
    float* dstp = (PASS == 1) ? g_t1 : dOut;
    int hw0 = h0*WID + w0 + gid;       // pixel (h0,   w0+gid)
    int hw1 = hw0 + WID;               // pixel (h0+1, w0+gid)
    float mx = 0.f;
    #pragma unroll
    for (int nt = 0; nt < 8; nt++) {
        int o0 = nt*8 + t4*2;
        float A0 = sAc[o0],   B0 = sBc[o0];
        float A1 = sAc[o0+1], B1 = sBc[o0+1];
        float t00 = (float)acc[nt][0] * A0 + B0;   // (hw0, o0)
        float t01 = (float)acc[nt][1] * A1 + B1;   // (hw0, o0+1)
        float t10 = (float)acc[nt][2] * A0 + B0;   // (hw1, o0)
        float t11 = (float)acc[nt][3] * A1 + B1;   // (hw1, o0+1)
        if (PASS == 2) {
            int c4i = o0 >> 2;          // word holding channels o0, o0+1
            int sh  = (o0 & 3) * 8;     // o0 byte shift; o0+1 at sh+8
            unsigned id0 = g_qxp[(n*16 + c4i)*HW + hw0];
            unsigned id1 = g_qxp[(n*16 + c4i)*HW + hw1];
            t00 += (float)((int)(int8_t)((id0 >> sh)     & 0xffu)) * sx;
            t01 += (float)((int)(int8_t)((id0 >> (sh+8)) & 0xffu)) * sx;
            t10 += (float)((int)(int8_t)((id1 >> sh)     & 0xffu)) * sx;
            t11 += (float)((int)(int8_t)((id1 >> (sh+8)) & 0xffu)) * sx;
        }
        dstp[(n*CC + o0    )*HW + hw0] = t00;
        dstp[(n*CC + o0 + 1)*HW + hw0] = t01;
        dstp[(n*CC + o0    )*HW + hw1] = t10;
        dstp[(n*CC + o0 + 1)*HW + hw1] = t11;
        mx = fmaxf(mx, fmaxf(fmaxf(t00, t01), fmaxf(t10, t11)));
    }
    mx = warpMaxPos(mx);
    if (lane == 0) smx[wid] = mx;
    __syncthreads();
    if (tid == 0) {
        float m = smx[0];
        #pragma unroll
        for (int i = 1; i < 7; i++) m = fmaxf(m, smx[i]);
        atomicMaxF((PASS == 1) ? &g_max_r1 : &g_max_r2, m);
    }
}

// ---------------- HM_act / HM_energy from factorized stats ----------------
__device__ __forceinline__ long long energyFor(const int* stats, const int* wsum, int cb) {
    int S   = stats[        cb];
    int r0  = stats[ 512  + cb];
    int r55 = stats[1024  + cb];
    int c0  = stats[1536  + cb];
    int c55 = stats[2048  + cb];
    int s00 = stats[2560  + cb];
    int s0b = stats[3072  + cb];
    int sb0 = stats[3584  + cb];
    int sbb = stats[4096  + cb];
    long long en = 0;
    #pragma unroll
    for (int kh = 0; kh < 3; kh++) {
        #pragma unroll
        for (int kw = 0; kw < 3; kw++) {
            int xs = S;
            if (kh == 2) xs -= r0;  else if (kh == 0) xs -= r55;
            if (kw == 2) xs -= c0;  else if (kw == 0) xs -= c55;
            if (kh == 2 && kw == 2) xs += s00;
            if (kh == 2 && kw == 0) xs += s0b;
            if (kh == 0 && kw == 2) xs += sb0;
            if (kh == 0 && kw == 0) xs += sbb;
            en += (long long)wsum[cb*9 + kh*3 + kw] * (long long)xs;
        }
    }
    return en;
}

// ---------------- final QuantReLU on d_out (in place) + finalize (block 1568) --
__global__ void __launch_bounds__(256) finalQuantFin(float* __restrict__ out) {
    cudaGridDependencySynchronize();
    if (blockIdx.x == 1568) {
        int t = threadIdx.x;
        long long act = 0, en = 0;
        for (int cb = t; cb < 512; cb += 256) {
            act += (long long)g_stats1[cb] + (long long)g_stats2[cb];
            en  += energyFor(g_stats1, g_wsum1, cb) + energyFor(g_stats2, g_wsum2, cb);
        }
        __shared__ long long sa[256], se[256];
        sa[t] = act; se[t] = en;
        __syncthreads();
        for (int step = 128; step; step >>= 1) {
            if (t < step) { sa[t] += sa[t + step]; se[t] += se[t + step]; }
            __syncthreads();
        }
        if (t == 0) {
            out[NN*CC*HW    ] = (float)sa[0];   // HM_act
            out[NN*CC*HW + 1] = (float)se[0];   // HM_energy
        }
        return;
    }
    float s = g_max_r2 * (1.f/255.f);
    float sinv = 1.0f / s;
    float4* o4 = (float4*)out;
    int base = blockIdx.x*256 + threadIdx.x;
    #pragma unroll
    for (int it = 0; it < 2; it++) {
        int i = base + it*401408;
        float4 v = o4[i];
        v.x = fminf(255.f, rintf(fmaxf(v.x, 0.f) * sinv)) * s;
        v.y = fminf(255.f, rintf(fmaxf(v.y, 0.f) * sinv)) * s;
        v.z = fminf(255.f, rintf(fmaxf(v.z, 0.f) * sinv)) * s;
        v.w = fminf(255.f, rintf(fmaxf(v.w, 0.f) * sinv)) * s;
        o4[i] = v;
    }
}

// ---------------- PDL launch helper ----------------
template <typename F, typename... Args>
static inline void launchPDL(F f, unsigned grid, unsigned block, Args... args) {
    cudaLaunchConfig_t cfg = {};
    cfg.gridDim  = dim3(grid, 1, 1);
    cfg.blockDim = dim3(block, 1, 1);
    cudaLaunchAttribute at[1];
    at[0].id = cudaLaunchAttributeProgrammaticStreamSerialization;
    at[0].val.programmaticStreamSerializationAllowed = 1;
    cfg.attrs = at;
    cfg.numAttrs = 1;
    cfg.stream = 0;
    cudaLaunchKernelEx(&cfg, f, args...);
}

// ---------------- launch ----------------
extern "C" void kernel_launch(void* const* d_in, const int* in_sizes, int n_in,
                              void* d_out, int out_size) {
    const float* x  = (const float*)d_in[0];
    const float* w1 = (const float*)d_in[1];
    const float* w2 = (const float*)d_in[2];
    const float* g1 = (const float*)d_in[3];
    const float* b1 = (const float*)d_in[4];
    const float* m1 = (const float*)d_in[5];
    const float* v1 = (const float*)d_in[6];
    const float* g2 = (const float*)d_in[7];
    const float* b2 = (const float*)d_in[8];
    const float* m2 = (const float*)d_in[9];
    const float* v2 = (const float*)d_in[10];
    float* out = (float*)d_out;

    reduceA<<<515, 256>>>((const float4*)x, w1, w2);
    launchPDL(quantStatsKernel<1>, 548, 256, x, w1, w2);
    launchPDL(convKernel<1>, 448, 224, g1, b1, m1, v1, (float*)nullptr);
    launchPDL(quantStatsKernel<2>, 512, 256, (const float*)nullptr, (const float*)nullptr, (const float*)nullptr);
    launchPDL(convKernel<2>, 448, 224, g2, b2, m2, v2, out);
    launchPDL(finalQuantFin, 1569, 256, out);
}

// round 12
// speedup vs baseline: 1.1689x; 1.0244x over previous
#include <cuda_runtime.h>
#include <cstdint>

// ---------------- problem constants ----------------
#define NN 16
#define CC 64
#define HW 3136       // 56*56
#define WID 56

// ---------------- device scratch ----------------
__device__ float g_maxabs_x, g_maxw1, g_maxw2, g_max_r1, g_max_r2;
__device__ float g_part[512];
__device__ unsigned g_qxp[NN*16*HW];     // packed int8 qx: (n, c4, hw), byte j = channel 4*c4+j
__device__ unsigned g_q1p[NN*16*HW];     // packed uint8 q1
__device__ float    g_t1 [NN*CC*HW];     // bn1 output (pre-relu), fp32
__device__ unsigned g_qw1p[9216];        // packed weights: [c4][pos][o]
__device__ unsigned g_qw2p[9216];
__device__ int g_wsum1[4608], g_wsum2[4608];     // [cb][pos], cb = c*8+bit
__device__ int g_stats1[9*512], g_stats2[9*512]; // 9 stats x 512 channel-bits

__device__ __forceinline__ void atomicMaxF(float* a, float v) {
    atomicMax((int*)a, __float_as_int(v));   // valid for non-negative floats
}
__device__ __forceinline__ float warpMaxPos(float v) {
    return __uint_as_float(__reduce_max_sync(0xffffffffu, __float_as_uint(v)));
}

// int8 tensor-core mma: D(16x8,s32) += A(16x32) * B(32x8)
template<int PASS>
__device__ __forceinline__ void MMA8(int* c, unsigned a0, unsigned a1, unsigned a2, unsigned a3,
                                     unsigned b0, unsigned b1) {
    if (PASS == 1)
        asm volatile(
            "mma.sync.aligned.m16n8k32.row.col.s32.s8.s8.s32 "
            "{%0,%1,%2,%3},{%4,%5,%6,%7},{%8,%9},{%0,%1,%2,%3};"
            : "+r"(c[0]), "+r"(c[1]), "+r"(c[2]), "+r"(c[3])
            : "r"(a0), "r"(a1), "r"(a2), "r"(a3), "r"(b0), "r"(b1));
    else
        asm volatile(
            "mma.sync.aligned.m16n8k32.row.col.s32.u8.s8.s32 "
            "{%0,%1,%2,%3},{%4,%5,%6,%7},{%8,%9},{%0,%1,%2,%3};"
            : "+r"(c[0]), "+r"(c[1]), "+r"(c[2]), "+r"(c[3])
            : "r"(a0), "r"(a1), "r"(a2), "r"(a3), "r"(b0), "r"(b1));
}

// ---------------- reduceA: partial max|x| (0..511), max|w| (512,513), init (514)
__global__ void reduceA(const float4* __restrict__ x,
                        const float* __restrict__ w1, const float* __restrict__ w2) {
    int b = blockIdx.x;
    if (b == 514) {
        if (threadIdx.x == 0) { g_max_r1 = 0.f; g_max_r2 = 0.f; }
        for (int i = threadIdx.x; i < 4608; i += 256) { g_stats1[i] = 0; g_stats2[i] = 0; }
        return;
    }
    float m = 0.f;
    if (b < 512) {
        const int n4 = NN*CC*HW/4;
        for (int i = b*256 + threadIdx.x; i < n4; i += 512*256) {
            float4 v = x[i];
            m = fmaxf(m, fmaxf(fmaxf(fabsf(v.x), fabsf(v.y)), fmaxf(fabsf(v.z), fabsf(v.w))));
        }
    } else {
        const float* w = (b == 513) ? w2 : w1;
        for (int i = threadIdx.x; i < 36864; i += 256) m = fmaxf(m, fabsf(w[i]));
    }
    m = warpMaxPos(m);
    __shared__ float sm[8];
    if ((threadIdx.x & 31) == 0) sm[threadIdx.x >> 5] = m;
    __syncthreads();
    if (threadIdx.x == 0) {
        float mm = sm[0];
        #pragma unroll
        for (int i = 1; i < 8; i++) mm = fmaxf(mm, sm[i]);
        if (b < 512) g_part[b] = mm;
        else if (b == 512) g_maxw1 = mm;
        else g_maxw2 = mm;
    }
}

// ---------------- fused quantize + bit stats (+ weight wsum blocks on PASS 1) --
// Nibble-packed counters: mask 0x11111111 counts bits k (low nibble) and k+4
// (high nibble) together; per-thread nibble totals <= 8 < 15 -> exact.
template<int PASS>
__global__ void __launch_bounds__(256) quantStatsKernel(const float* __restrict__ xin,
                                                        const float* __restrict__ w1,
                                                        const float* __restrict__ w2) {
    cudaGridDependencySynchronize();
    const unsigned M = 0x01010101u;
    const unsigned N4 = 0x11111111u;
    if (PASS == 1 && blockIdx.x >= 512) {
        int item = (blockIdx.x - 512)*8 + (threadIdx.x >> 5);
        int lane = threadIdx.x & 31;
        int sel = item / 144;
        int g   = item - sel*144;
        int c4  = g / 9, pos = g - c4*9;
        const float* w = sel ? w2 : w1;
        float s = (sel ? g_maxw2 : g_maxw1) * (1.0f/127.0f);
        unsigned* wpout = sel ? g_qw2p : g_qw1p;
        unsigned wds[2];
        #pragma unroll
        for (int h = 0; h < 2; h++) {
            int o = lane + 32*h;
            unsigned word = 0;
            #pragma unroll
            for (int j = 0; j < 4; j++) {
                float q = rintf(w[o*576 + (c4*4 + j)*9 + pos] / s);
                q = fminf(127.f, fmaxf(-127.f, q));
                word |= (((unsigned)(int)q) & 0xffu) << (8*j);
            }
            wpout[c4*576 + pos*64 + o] = word;
            wds[h] = word;
        }
        unsigned acc[8];
        #pragma unroll
        for (int k = 0; k < 8; k++)
            acc[k] = __reduce_add_sync(0xffffffffu, ((wds[0] >> k) & M) + ((wds[1] >> k) & M));
        int j = lane >> 3, k = lane & 7;
        int* wsum = sel ? g_wsum2 : g_wsum1;
        wsum[((c4*4 + j)*8 + k)*9 + pos] = (int)((acc[k] >> (8*j)) & 0xffu);
        return;
    }

    int n    = blockIdx.x >> 5;
    int rem  = blockIdx.x & 31;
    int c4   = rem >> 1;
    int half = rem & 1;
    const float* src = (PASS == 1) ? xin : (const float*)g_t1;
    const float4* s0 = (const float4*)(src + (size_t)(n*CC + c4*4)*HW);
    unsigned* qp = (PASS == 1) ? g_qxp : g_q1p;
    uint4* dst = (uint4*)(qp + (size_t)(n*16 + c4)*HW);

    __shared__ unsigned scCor[128];
    __shared__ unsigned ws[8*48];
    __shared__ float sMaxW[8];

    if (PASS == 1) {
        float mloc = 0.f;
        for (int i = threadIdx.x; i < 512; i += 256) mloc = fmaxf(mloc, g_part[i]);
        mloc = warpMaxPos(mloc);
        if ((threadIdx.x & 31) == 0) sMaxW[threadIdx.x >> 5] = mloc;
    }
    if (threadIdx.x < 128) scCor[threadIdx.x] = 0;
    __syncthreads();

    float s;
    if (PASS == 1) {
        float mm = sMaxW[0];
        #pragma unroll
        for (int i = 1; i < 8; i++) mm = fmaxf(mm, sMaxW[i]);
        if (blockIdx.x == 0 && threadIdx.x == 0) g_maxabs_x = mm;
        s = mm * (1.0f/127.0f);
    } else {
        s = g_max_r1 * (1.0f/255.0f);
    }
    float sinv = 1.0f / s;

    // quantize one value to a byte (int-domain clamp; cvt.rni == rintf rounding)
    auto qByte = [&](float v) -> unsigned {
        int q;
        if (PASS == 1) {
            q = __float2int_rn(v * sinv);
            q = ::max(-127, ::min(127, q));
        } else {
            q = __float2int_rn(fmaxf(v, 0.f) * sinv);
            q = ::min(255, q);
        }
        return (unsigned)q & 0xffu;
    };
    auto quantQuad = [&](int i, unsigned w[4]) {
        float4 f0 = s0[i];
        float4 f1 = s0[784 + i];
        float4 f2 = s0[1568 + i];
        float4 f3 = s0[2352 + i];
        w[0] = qByte(f0.x) | (qByte(f1.x) << 8) | (qByte(f2.x) << 16) | (qByte(f3.x) << 24);
        w[1] = qByte(f0.y) | (qByte(f1.y) << 8) | (qByte(f2.y) << 16) | (qByte(f3.y) << 24);
        w[2] = qByte(f0.z) | (qByte(f1.z) << 8) | (qByte(f2.z) << 16) | (qByte(f3.z) << 24);
        w[3] = qByte(f0.w) | (qByte(f1.w) << 8) | (qByte(f2.w) << 16) | (qByte(f3.w) << 24);
    };

    unsigned accN[4] = {0,0,0,0};
    int ibase = half * 392;
    for (int li = threadIdx.x; li < 392; li += 256) {
        int i = ibase + li;
        unsigned w[4];
        quantQuad(i, w);
        dst[i] = make_uint4(w[0], w[1], w[2], w[3]);
        #pragma unroll
        for (int k = 0; k < 4; k++)
            accN[k] += ((w[0]>>k)&N4) + ((w[1]>>k)&N4) + ((w[2]>>k)&N4) + ((w[3]>>k)&N4);
    }

    unsigned aBN[4] = {0,0,0,0};
    int warp = threadIdx.x >> 5;
    int lane = threadIdx.x & 31;
    if (warp == 0 && lane < 14) {
        int i = half ? 770 + lane : lane;
        unsigned w[4];
        quantQuad(i, w);
        #pragma unroll
        for (int k = 0; k < 4; k++)
            aBN[k] += ((w[0]>>k)&N4) + ((w[1]>>k)&N4) + ((w[2]>>k)&N4) + ((w[3]>>k)&N4);
        if (lane == 0) {
            int corner = half ? 2 : 0;  unsigned u = w[0];
            #pragma unroll
            for (int l = 0; l < 32; l++) atomicAdd(&scCor[corner*32 + l], (u >> l) & 1u);
        }
        if (lane == 13) {
            int corner = half ? 3 : 1;  unsigned u = w[3];
            #pragma unroll
            for (int l = 0; l < 32; l++) atomicAdd(&scCor[corner*32 + l], (u >> l) & 1u);
        }
    } else if (warp == 1 && lane < 28) {
        int i = ibase + lane*14;
        unsigned w[4];
        quantQuad(i, w);
        #pragma unroll
        for (int k = 0; k < 4; k++) aBN[k] += (w[0] >> k) & N4;
    } else if (warp == 2 && lane < 28) {
        int i = ibase + lane*14 + 13;
        unsigned w[4];
        quantQuad(i, w);
        #pragma unroll
        for (int k = 0; k < 4; k++) aBN[k] += (w[3] >> k) & N4;
    }

    // unpack nibbles -> byte lanes (<=8), then 16-bit split + REDUX
    unsigned aLo[8], aHi[8], aB[8];
    #pragma unroll
    for (int k = 0; k < 4; k++) {
        unsigned lo = accN[k] & 0x0F0F0F0Fu;
        unsigned hi = (accN[k] >> 4) & 0x0F0F0F0Fu;
        aLo[k]   = __reduce_add_sync(0xffffffffu, lo & 0x00FF00FFu);
        aHi[k]   = __reduce_add_sync(0xffffffffu, (lo >> 8) & 0x00FF00FFu);
        aLo[k+4] = __reduce_add_sync(0xffffffffu, hi & 0x00FF00FFu);
        aHi[k+4] = __reduce_add_sync(0xffffffffu, (hi >> 8) & 0x00FF00FFu);
        aB[k]    = __reduce_add_sync(0xffffffffu, aBN[k] & 0x0F0F0F0Fu);
        aB[k+4]  = __reduce_add_sync(0xffffffffu, (aBN[k] >> 4) & 0x0F0F0F0Fu);
    }
    if (lane == 0) {
        #pragma unroll
        for (int k = 0; k < 8; k++) {
            ws[warp*48 +     k] = aLo[k];
            ws[warp*48 + 8 + k] = aHi[k];
        }
        #pragma unroll
        for (int slot = 0; slot < 4; slot++)
            #pragma unroll
            for (int k = 0; k < 8; k++) ws[warp*48 + 16 + slot*8 + k] = 0;
        int region = (warp == 0) ? (half ? 2 : 1) : (warp == 1) ? 3 : (warp == 2) ? 4 : 0;
        if (region) {
            #pragma unroll
            for (int k = 0; k < 8; k++) ws[warp*48 + 16 + (region-1)*8 + k] = aB[k];
        }
    }
    __syncthreads();

    int* stats = (PASS == 1) ? g_stats1 : g_stats2;
    if (threadIdx.x < 8) {
        int k = threadIdx.x;
        unsigned vlo = 0, vhi = 0;
        #pragma unroll
        for (int wp = 0; wp < 8; wp++) {
            vlo += ws[wp*48 +     k];
            vhi += ws[wp*48 + 8 + k];
        }
        atomicAdd(&stats[(c4*4 + 0)*8 + k], (int)(vlo & 0xffffu));
        atomicAdd(&stats[(c4*4 + 2)*8 + k], (int)(vlo >> 16));
        atomicAdd(&stats[(c4*4 + 1)*8 + k], (int)(vhi & 0xffffu));
        atomicAdd(&stats[(c4*4 + 3)*8 + k], (int)(vhi >> 16));
    } else if (threadIdx.x < 40) {
        int t2   = threadIdx.x - 8;
        int sidx = 1 + (t2 >> 3);
        int k    = t2 & 7;
        unsigned v = 0;
        #pragma unroll
        for (int wp = 0; wp < 8; wp++) v += ws[wp*48 + 8 + sidx*8 + k];
        #pragma unroll
        for (int j = 0; j < 4; j++)
            atomicAdd(&stats[sidx*512 + (c4*4 + j)*8 + k], (int)((v >> (8*j)) & 0xffu));
    }
    if (threadIdx.x < 128) {
        int corner = threadIdx.x >> 5;
        int l = threadIdx.x & 31;
        int j = l >> 3, k = l & 7;
        int v = (int)scCor[threadIdx.x];
        if (v) atomicAdd(&stats[(5 + corner)*512 + (c4*4 + j)*8 + k], v);
    }
}

// ---------------- int8 TENSOR-CORE conv (mma.sync m16n8k32) + BN (+identity) ----
// Single staging phase: ALL weights (16x576 words, XOR-swizzled, uint4) + full
// input tile (16 c4 x 4 rows x 58 cols) in dynamic smem; one __syncthreads.
template<int PASS>
__global__ void __launch_bounds__(224) convKernel(
    const float* __restrict__ gamma, const float* __restrict__ beta,
    const float* __restrict__ mean,  const float* __restrict__ var,
    float* __restrict__ dOut)
{
    cudaGridDependencySynchronize();
    const unsigned* __restrict__ inP = (PASS == 1) ? g_qxp : g_q1p;
    const unsigned* __restrict__ wP  = (PASS == 1) ? g_qw1p : g_qw2p;
    int n  = blockIdx.x / 28;
    int h0 = (blockIdx.x - n*28) * 2;

    extern __shared__ unsigned dynS[];
    unsigned* sW  = dynS;            // 16*576 = 9216 words
    unsigned* sIn = dynS + 9216;     // 16*232 = 3712 words
    __shared__ float sAc[64], sBc[64];
    __shared__ float smx[7];

    int tid  = threadIdx.x;
    int lane = tid & 31, wid = tid >> 5;
    int gid  = lane >> 2, t4 = lane & 3;
    int w0   = wid * 8;

    float sp1, sx = 0.f;
    if (PASS == 1) {
        sp1 = (g_maxabs_x * (1.f/127.f)) * (g_maxw1 * (1.f/127.f));
    } else {
        sp1 = (g_max_r1 * (1.f/255.f)) * (g_maxw2 * (1.f/127.f));
        sx  = g_maxabs_x * (1.f/127.f);
    }
    if (tid < 64) {
        float inv = gamma[tid] / sqrtf(var[tid] + 1e-5f);
        sAc[tid] = sp1 * inv;
        sBc[tid] = beta[tid] - mean[tid]*inv;
    }

    // stage weights (uint4; XOR swizzle preserves 4-groups)
    {
        const uint4* wp4 = (const uint4*)wP;
        uint4* sw4 = (uint4*)sW;
        for (int i4 = tid; i4 < 2304; i4 += 224) {
            int i = i4 << 2;
            int o = i & 63;
            int cp = i >> 6;
            int c4l = cp / 9;
            int pos = cp - c4l*9;
            uint4 v = wp4[i4];
            sw4[(c4l*576 + (pos << 6) + (o ^ ((c4l & 3) << 3))) >> 2] = v;
        }
    }
    // stage input tile (rows h0-1 .. h0+2 with halo)
    for (int p = tid; p < 3712; p += 224) {
        int c4r = p / 58;
        int cc  = p - c4r*58;
        int rr  = c4r & 3;
        int c4l = c4r >> 2;
        int gr = h0 - 1 + rr, gc = cc - 1;
        unsigned v = 0;
        if ((unsigned)gr < 56u && (unsigned)gc < 56u)
            v = inP[(n*16 + c4l)*HW + gr*WID + gc];
        sIn[p] = v;
    }
    __syncthreads();

    int acc[8][4];
    #pragma unroll
    for (int nt = 0; nt < 8; nt++)
        #pragma unroll
        for (int r = 0; r < 4; r++) acc[nt][r] = 0;

    unsigned sw8 = (unsigned)(t4 << 3);
    #pragma unroll
    for (int cg = 0; cg < 2; cg++) {
        int cb = cg * 8;
        #pragma unroll
        for (int ph = 0; ph < 3; ph++) {
            #pragma unroll
            for (int pw = 0; pw < 3; pw++) {
                int pos = ph*3 + pw;
                int ccol = w0 + gid + pw;
                unsigned a0 = sIn[(cb + t4    )*232 +  ph   *58 + ccol];
                unsigned a1 = sIn[(cb + t4    )*232 + (ph+1)*58 + ccol];
                unsigned a2 = sIn[(cb + 4 + t4)*232 +  ph   *58 + ccol];
                unsigned a3 = sIn[(cb + 4 + t4)*232 + (ph+1)*58 + ccol];
                const unsigned* sWb0 = sW + (cb + t4    )*576 + pos*64;
                const unsigned* sWb1 = sW + (cb + 4 + t4)*576 + pos*64;
                #pragma unroll
                for (int nt = 0; nt < 8; nt++) {
                    int o = nt*8 + gid;
                    unsigned b0 = sWb0[o ^ sw8];
                    unsigned b1 = sWb1[o ^ sw8];
                    MMA8<PASS>(acc[nt], a0, a1, a2, a3, b0, b1);
                }
            }
        }
    }

    // epilogue: BN (+identity), store, max
    float* dstp = (PASS == 1) ? g_t1 : dOut;
    int hw0 = h0*WID + w0 + gid;
    int hw1 = hw0 + WID;
    float mx = 0.f;
    #pragma unroll
    for (int nt = 0; nt < 8; nt++) {
        int o0 = nt*8 + t4*2;
        float A0 = sAc[o0],   B0 = sBc[o0];
        float A1 = sAc[o0+1], B1 = sBc[o0+1];
        float t00 = (float)acc[nt][0] * A0 + B0;
        float t01 = (float)acc[nt][1] * A1 + B1;
        float t10 = (float)acc[nt][2] * A0 + B0;
        float t11 = (float)acc[nt][3] * A1 + B1;
        if (PASS == 2) {
            int c4i = o0 >> 2;
            int sh  = (o0 & 3) * 8;
            unsigned id0 = g_qxp[(n*16 + c4i)*HW + hw0];
            unsigned id1 = g_qxp[(n*16 + c4i)*HW + hw1];
            t00 += (float)((int)(int8_t)((id0 >> sh)     & 0xffu)) * sx;
            t01 += (float)((int)(int8_t)((id0 >> (sh+8)) & 0xffu)) * sx;
            t10 += (float)((int)(int8_t)((id1 >> sh)     & 0xffu)) * sx;
            t11 += (float)((int)(int8_t)((id1 >> (sh+8)) & 0xffu)) * sx;
        }
        dstp[(n*CC + o0    )*HW + hw0] = t00;
        dstp[(n*CC + o0 + 1)*HW + hw0] = t01;
        dstp[(n*CC + o0    )*HW + hw1] = t10;
        dstp[(n*CC + o0 + 1)*HW + hw1] = t11;
        mx = fmaxf(mx, fmaxf(fmaxf(t00, t01), fmaxf(t10, t11)));
    }
    mx = warpMaxPos(mx);
    if (lane == 0) smx[wid] = mx;
    __syncthreads();
    if (tid == 0) {
        float m = smx[0];
        #pragma unroll
        for (int i = 1; i < 7; i++) m = fmaxf(m, smx[i]);
        atomicMaxF((PASS == 1) ? &g_max_r1 : &g_max_r2, m);
    }
}

// ---------------- HM_act / HM_energy from factorized stats ----------------
__device__ __forceinline__ long long energyFor(const int* stats, const int* wsum, int cb) {
    int S   = stats[        cb];
    int r0  = stats[ 512  + cb];
    int r55 = stats[1024  + cb];
    int c0  = stats[1536  + cb];
    int c55 = stats[2048  + cb];
    int s00 = stats[2560  + cb];
    int s0b = stats[3072  + cb];
    int sb0 = stats[3584  + cb];
    int sbb = stats[4096  + cb];
    long long en = 0;
    #pragma unroll
    for (int kh = 0; kh < 3; kh++) {
        #pragma unroll
        for (int kw = 0; kw < 3; kw++) {
            int xs = S;
            if (kh == 2) xs -= r0;  else if (kh == 0) xs -= r55;
            if (kw == 2) xs -= c0;  else if (kw == 0) xs -= c55;
            if (kh == 2 && kw == 2) xs += s00;
            if (kh == 2 && kw == 0) xs += s0b;
            if (kh == 0 && kw == 2) xs += sb0;
            if (kh == 0 && kw == 0) xs += sbb;
            en += (long long)wsum[cb*9 + kh*3 + kw] * (long long)xs;
        }
    }
    return en;
}

// ---------------- final QuantReLU on d_out (in place) + finalize (block 1568) --
__global__ void __launch_bounds__(256) finalQuantFin(float* __restrict__ out) {
    cudaGridDependencySynchronize();
    if (blockIdx.x == 1568) {
        int t = threadIdx.x;
        long long act = 0, en = 0;
        for (int cb = t; cb < 512; cb += 256) {
            act += (long long)g_stats1[cb] + (long long)g_stats2[cb];
            en  += energyFor(g_stats1, g_wsum1, cb) + energyFor(g_stats2, g_wsum2, cb);
        }
        __shared__ long long sa[256], se[256];
        sa[t] = act; se[t] = en;
        __syncthreads();
        for (int step = 128; step; step >>= 1) {
            if (t < step) { sa[t] += sa[t + step]; se[t] += se[t + step]; }
            __syncthreads();
        }
        if (t == 0) {
            out[NN*CC*HW    ] = (float)sa[0];   // HM_act
            out[NN*CC*HW + 1] = (float)se[0];   // HM_energy
        }
        return;
    }
    float s = g_max_r2 * (1.f/255.f);
    float sinv = 1.0f / s;
    float4* o4 = (float4*)out;
    int base = blockIdx.x*256 + threadIdx.x;
    #pragma unroll
    for (int it = 0; it < 2; it++) {
        int i = base + it*401408;
        float4 v = o4[i];
        v.x = (float)::min(255, __float2int_rn(fmaxf(v.x, 0.f) * sinv)) * s;
        v.y = (float)::min(255, __float2int_rn(fmaxf(v.y, 0.f) * sinv)) * s;
        v.z = (float)::min(255, __float2int_rn(fmaxf(v.z, 0.f) * sinv)) * s;
        v.w = (float)::min(255, __float2int_rn(fmaxf(v.w, 0.f) * sinv)) * s;
        o4[i] = v;
    }
}

// ---------------- PDL launch helper ----------------
template <typename F, typename... Args>
static inline void launchPDL(F f, unsigned grid, unsigned block, unsigned smem, Args... args) {
    cudaLaunchConfig_t cfg = {};
    cfg.gridDim  = dim3(grid, 1, 1);
    cfg.blockDim = dim3(block, 1, 1);
    cfg.dynamicSmemBytes = smem;
    cudaLaunchAttribute at[1];
    at[0].id = cudaLaunchAttributeProgrammaticStreamSerialization;
    at[0].val.programmaticStreamSerializationAllowed = 1;
    cfg.attrs = at;
    cfg.numAttrs = 1;
    cfg.stream = 0;
    cudaLaunchKernelEx(&cfg, f, args...);
}

#define CONV_SMEM ((9216 + 3712) * 4)

// ---------------- launch ----------------
extern "C" void kernel_launch(void* const* d_in, const int* in_sizes, int n_in,
                              void* d_out, int out_size) {
    const float* x  = (const float*)d_in[0];
    const float* w1 = (const float*)d_in[1];
    const float* w2 = (const float*)d_in[2];
    const float* g1 = (const float*)d_in[3];
    const float* b1 = (const float*)d_in[4];
    const float* m1 = (const float*)d_in[5];
    const float* v1 = (const float*)d_in[6];
    const float* g2 = (const float*)d_in[7];
    const float* b2 = (const float*)d_in[8];
    const float* m2 = (const float*)d_in[9];
    const float* v2 = (const float*)d_in[10];
    float* out = (float*)d_out;

    cudaFuncSetAttribute(convKernel<1>, cudaFuncAttributeMaxDynamicSharedMemorySize, CONV_SMEM);
    cudaFuncSetAttribute(convKernel<2>, cudaFuncAttributeMaxDynamicSharedMemorySize, CONV_SMEM);

    reduceA<<<515, 256>>>((const float4*)x, w1, w2);
    launchPDL(quantStatsKernel<1>, 548, 256, 0, x, w1, w2);
    launchPDL(convKernel<1>, 448, 224, CONV_SMEM, g1, b1, m1, v1, (float*)nullptr);
    launchPDL(quantStatsKernel<2>, 512, 256, 0, (const float*)nullptr, (const float*)nullptr, (const float*)nullptr);
    launchPDL(convKernel<2>, 448, 224, CONV_SMEM, g2, b2, m2, v2, out);
    launchPDL(finalQuantFin, 1569, 256, 0, out);
}

// round 13
// speedup vs baseline: 1.1704x; 1.0013x over previous
#include <cuda_runtime.h>
#include <cstdint>

// ---------------- problem constants ----------------
#define NN 16
#define CC 64
#define HW 3136       // 56*56
#define WID 56

// ---------------- device scratch ----------------
__device__ float g_maxabs_x, g_maxw1, g_maxw2, g_max_r1, g_max_r2;
__device__ float g_part[512];
__device__ unsigned g_qxp[NN*16*HW];     // packed int8 qx: (n, c4, hw), byte j = channel 4*c4+j
__device__ unsigned g_q1p[NN*16*HW];     // packed uint8 q1
__device__ float    g_t1 [NN*CC*HW];     // bn1 output (pre-relu), fp32
__device__ unsigned g_qw1p[9216];        // packed weights: [c4][pos][o]
__device__ unsigned g_qw2p[9216];
__device__ int g_wsum1[4608], g_wsum2[4608];     // [cb][pos], cb = c*8+bit
__device__ int g_stats1[9*512], g_stats2[9*512]; // 9 stats x 512 channel-bits

__device__ __forceinline__ void atomicMaxF(float* a, float v) {
    atomicMax((int*)a, __float_as_int(v));   // valid for non-negative floats
}
__device__ __forceinline__ float warpMaxPos(float v) {
    return __uint_as_float(__reduce_max_sync(0xffffffffu, __float_as_uint(v)));
}

// int8 tensor-core mma: D(16x8,s32) += A(16x32) * B(32x8)
template<int PASS>
__device__ __forceinline__ void MMA8(int* c, unsigned a0, unsigned a1, unsigned a2, unsigned a3,
                                     unsigned b0, unsigned b1) {
    if (PASS == 1)
        asm volatile(
            "mma.sync.aligned.m16n8k32.row.col.s32.s8.s8.s32 "
            "{%0,%1,%2,%3},{%4,%5,%6,%7},{%8,%9},{%0,%1,%2,%3};"
            : "+r"(c[0]), "+r"(c[1]), "+r"(c[2]), "+r"(c[3])
            : "r"(a0), "r"(a1), "r"(a2), "r"(a3), "r"(b0), "r"(b1));
    else
        asm volatile(
            "mma.sync.aligned.m16n8k32.row.col.s32.u8.s8.s32 "
            "{%0,%1,%2,%3},{%4,%5,%6,%7},{%8,%9},{%0,%1,%2,%3};"
            : "+r"(c[0]), "+r"(c[1]), "+r"(c[2]), "+r"(c[3])
            : "r"(a0), "r"(a1), "r"(a2), "r"(a3), "r"(b0), "r"(b1));
}

// ---------------- reduceA: partial max|x| (0..511), max|w| (512,513), init (514)
__global__ void reduceA(const float4* __restrict__ x,
                        const float* __restrict__ w1, const float* __restrict__ w2) {
    int b = blockIdx.x;
    if (b == 514) {
        if (threadIdx.x == 0) { g_max_r1 = 0.f; g_max_r2 = 0.f; }
        for (int i = threadIdx.x; i < 4608; i += 256) { g_stats1[i] = 0; g_stats2[i] = 0; }
        return;
    }
    float m = 0.f;
    if (b < 512) {
        const int n4 = NN*CC*HW/4;
        for (int i = b*256 + threadIdx.x; i < n4; i += 512*256) {
            float4 v = x[i];
            m = fmaxf(m, fmaxf(fmaxf(fabsf(v.x), fabsf(v.y)), fmaxf(fabsf(v.z), fabsf(v.w))));
        }
    } else {
        const float* w = (b == 513) ? w2 : w1;
        for (int i = threadIdx.x; i < 36864; i += 256) m = fmaxf(m, fabsf(w[i]));
    }
    m = warpMaxPos(m);
    __shared__ float sm[8];
    if ((threadIdx.x & 31) == 0) sm[threadIdx.x >> 5] = m;
    __syncthreads();
    if (threadIdx.x == 0) {
        float mm = sm[0];
        #pragma unroll
        for (int i = 1; i < 8; i++) mm = fmaxf(mm, sm[i]);
        if (b < 512) g_part[b] = mm;
        else if (b == 512) g_maxw1 = mm;
        else g_maxw2 = mm;
    }
}

// ---------------- fused quantize + bit stats (+ weight wsum blocks on PASS 1) --
// Nibble-packed counters (mask 0x11111111): per-thread nibble totals <= 8 < 15.
template<int PASS>
__global__ void __launch_bounds__(256) quantStatsKernel(const float* __restrict__ xin,
                                                        const float* __restrict__ w1,
                                                        const float* __restrict__ w2) {
    cudaGridDependencySynchronize();
    const unsigned M = 0x01010101u;
    const unsigned N4 = 0x11111111u;
    if (PASS == 1 && blockIdx.x >= 512) {
        int item = (blockIdx.x - 512)*8 + (threadIdx.x >> 5);
        int lane = threadIdx.x & 31;
        int sel = item / 144;
        int g   = item - sel*144;
        int c4  = g / 9, pos = g - c4*9;
        const float* w = sel ? w2 : w1;
        float s = (sel ? g_maxw2 : g_maxw1) * (1.0f/127.0f);
        unsigned* wpout = sel ? g_qw2p : g_qw1p;
        unsigned wds[2];
        #pragma unroll
        for (int h = 0; h < 2; h++) {
            int o = lane + 32*h;
            unsigned word = 0;
            #pragma unroll
            for (int j = 0; j < 4; j++) {
                float q = rintf(w[o*576 + (c4*4 + j)*9 + pos] / s);
                q = fminf(127.f, fmaxf(-127.f, q));
                word |= (((unsigned)(int)q) & 0xffu) << (8*j);
            }
            wpout[c4*576 + pos*64 + o] = word;
            wds[h] = word;
        }
        unsigned acc[8];
        #pragma unroll
        for (int k = 0; k < 8; k++)
            acc[k] = __reduce_add_sync(0xffffffffu, ((wds[0] >> k) & M) + ((wds[1] >> k) & M));
        int j = lane >> 3, k = lane & 7;
        int* wsum = sel ? g_wsum2 : g_wsum1;
        wsum[((c4*4 + j)*8 + k)*9 + pos] = (int)((acc[k] >> (8*j)) & 0xffu);
        return;
    }

    int n    = blockIdx.x >> 5;
    int rem  = blockIdx.x & 31;
    int c4   = rem >> 1;
    int half = rem & 1;
    const float* src = (PASS == 1) ? xin : (const float*)g_t1;
    const float4* s0 = (const float4*)(src + (size_t)(n*CC + c4*4)*HW);
    unsigned* qp = (PASS == 1) ? g_qxp : g_q1p;
    uint4* dst = (uint4*)(qp + (size_t)(n*16 + c4)*HW);

    __shared__ unsigned scCor[128];
    __shared__ unsigned ws[8*48];
    __shared__ float sMaxW[8];

    if (PASS == 1) {
        float mloc = 0.f;
        for (int i = threadIdx.x; i < 512; i += 256) mloc = fmaxf(mloc, g_part[i]);
        mloc = warpMaxPos(mloc);
        if ((threadIdx.x & 31) == 0) sMaxW[threadIdx.x >> 5] = mloc;
    }
    if (threadIdx.x < 128) scCor[threadIdx.x] = 0;
    __syncthreads();

    float s;
    if (PASS == 1) {
        float mm = sMaxW[0];
        #pragma unroll
        for (int i = 1; i < 8; i++) mm = fmaxf(mm, sMaxW[i]);
        if (blockIdx.x == 0 && threadIdx.x == 0) g_maxabs_x = mm;
        s = mm * (1.0f/127.0f);
    } else {
        s = g_max_r1 * (1.0f/255.0f);
    }
    float sinv = 1.0f / s;

    auto qByte = [&](float v) -> unsigned {
        int q;
        if (PASS == 1) {
            q = __float2int_rn(v * sinv);
            q = ::max(-127, ::min(127, q));
        } else {
            q = __float2int_rn(fmaxf(v, 0.f) * sinv);
            q = ::min(255, q);
        }
        return (unsigned)q & 0xffu;
    };
    auto quantFromF = [&](const float4 f[4], unsigned w[4]) {
        w[0] = qByte(f[0].x) | (qByte(f[1].x) << 8) | (qByte(f[2].x) << 16) | (qByte(f[3].x) << 24);
        w[1] = qByte(f[0].y) | (qByte(f[1].y) << 8) | (qByte(f[2].y) << 16) | (qByte(f[3].y) << 24);
        w[2] = qByte(f[0].z) | (qByte(f[1].z) << 8) | (qByte(f[2].z) << 16) | (qByte(f[3].z) << 24);
        w[3] = qByte(f[0].w) | (qByte(f[1].w) << 8) | (qByte(f[2].w) << 16) | (qByte(f[3].w) << 24);
    };
    auto quantQuad = [&](int i, unsigned w[4]) {
        float4 f[4];
        f[0] = s0[i]; f[1] = s0[784 + i]; f[2] = s0[1568 + i]; f[3] = s0[2352 + i];
        quantFromF(f, w);
    };

    // -------- main loop: 2-quad explicit ILP (indices tid and tid+256) --------
    unsigned accN[4] = {0,0,0,0};
    int ibase = half * 392;
    {
        int li0 = threadIdx.x;
        int i0 = ibase + li0;
        bool has2 = (li0 + 256) < 392;
        int i1 = i0 + 256;
        float4 fA[4], fB[4];
        fA[0] = s0[i0]; fA[1] = s0[784 + i0]; fA[2] = s0[1568 + i0]; fA[3] = s0[2352 + i0];
        if (has2) {
            fB[0] = s0[i1]; fB[1] = s0[784 + i1]; fB[2] = s0[1568 + i1]; fB[3] = s0[2352 + i1];
        }
        unsigned w[4];
        quantFromF(fA, w);
        dst[i0] = make_uint4(w[0], w[1], w[2], w[3]);
        #pragma unroll
        for (int k = 0; k < 4; k++)
            accN[k] += ((w[0]>>k)&N4) + ((w[1]>>k)&N4) + ((w[2]>>k)&N4) + ((w[3]>>k)&N4);
        if (has2) {
            quantFromF(fB, w);
            dst[i1] = make_uint4(w[0], w[1], w[2], w[3]);
            #pragma unroll
            for (int k = 0; k < 4; k++)
                accN[k] += ((w[0]>>k)&N4) + ((w[1]>>k)&N4) + ((w[2]>>k)&N4) + ((w[3]>>k)&N4);
        }
    }

    // -------- borders: warp 0 = row border, warp 1 = col 0, warp 2 = col 55 ---
    unsigned aBN[4] = {0,0,0,0};
    int warp = threadIdx.x >> 5;
    int lane = threadIdx.x & 31;
    if (warp == 0 && lane < 14) {
        int i = half ? 770 + lane : lane;
        unsigned w[4];
        quantQuad(i, w);
        #pragma unroll
        for (int k = 0; k < 4; k++)
            aBN[k] += ((w[0]>>k)&N4) + ((w[1]>>k)&N4) + ((w[2]>>k)&N4) + ((w[3]>>k)&N4);
        if (lane == 0) {
            int corner = half ? 2 : 0;  unsigned u = w[0];
            #pragma unroll
            for (int l = 0; l < 32; l++) atomicAdd(&scCor[corner*32 + l], (u >> l) & 1u);
        }
        if (lane == 13) {
            int corner = half ? 3 : 1;  unsigned u = w[3];
            #pragma unroll
            for (int l = 0; l < 32; l++) atomicAdd(&scCor[corner*32 + l], (u >> l) & 1u);
        }
    } else if (warp == 1 && lane < 28) {
        int i = ibase + lane*14;
        unsigned w[4];
        quantQuad(i, w);
        #pragma unroll
        for (int k = 0; k < 4; k++) aBN[k] += (w[0] >> k) & N4;
    } else if (warp == 2 && lane < 28) {
        int i = ibase + lane*14 + 13;
        unsigned w[4];
        quantQuad(i, w);
        #pragma unroll
        for (int k = 0; k < 4; k++) aBN[k] += (w[3] >> k) & N4;
    }

    // unpack nibbles -> byte lanes (<=8), then 16-bit split + REDUX
    unsigned aLo[8], aHi[8], aB[8];
    #pragma unroll
    for (int k = 0; k < 4; k++) {
        unsigned lo = accN[k] & 0x0F0F0F0Fu;
        unsigned hi = (accN[k] >> 4) & 0x0F0F0F0Fu;
        aLo[k]   = __reduce_add_sync(0xffffffffu, lo & 0x00FF00FFu);
        aHi[k]   = __reduce_add_sync(0xffffffffu, (lo >> 8) & 0x00FF00FFu);
        aLo[k+4] = __reduce_add_sync(0xffffffffu, hi & 0x00FF00FFu);
        aHi[k+4] = __reduce_add_sync(0xffffffffu, (hi >> 8) & 0x00FF00FFu);
        aB[k]    = __reduce_add_sync(0xffffffffu, aBN[k] & 0x0F0F0F0Fu);
        aB[k+4]  = __reduce_add_sync(0xffffffffu, (aBN[k] >> 4) & 0x0F0F0F0Fu);
    }
    if (lane == 0) {
        #pragma unroll
        for (int k = 0; k < 8; k++) {
            ws[warp*48 +     k] = aLo[k];
            ws[warp*48 + 8 + k] = aHi[k];
        }
        #pragma unroll
        for (int slot = 0; slot < 4; slot++)
            #pragma unroll
            for (int k = 0; k < 8; k++) ws[warp*48 + 16 + slot*8 + k] = 0;
        int region = (warp == 0) ? (half ? 2 : 1) : (warp == 1) ? 3 : (warp == 2) ? 4 : 0;
        if (region) {
            #pragma unroll
            for (int k = 0; k < 8; k++) ws[warp*48 + 16 + (region-1)*8 + k] = aB[k];
        }
    }
    __syncthreads();

    int* stats = (PASS == 1) ? g_stats1 : g_stats2;
    if (threadIdx.x < 8) {
        int k = threadIdx.x;
        unsigned vlo = 0, vhi = 0;
        #pragma unroll
        for (int wp = 0; wp < 8; wp++) {
            vlo += ws[wp*48 +     k];
            vhi += ws[wp*48 + 8 + k];
        }
        atomicAdd(&stats[(c4*4 + 0)*8 + k], (int)(vlo & 0xffffu));
        atomicAdd(&stats[(c4*4 + 2)*8 + k], (int)(vlo >> 16));
        atomicAdd(&stats[(c4*4 + 1)*8 + k], (int)(vhi & 0xffffu));
        atomicAdd(&stats[(c4*4 + 3)*8 + k], (int)(vhi >> 16));
    } else if (threadIdx.x < 40) {
        int t2   = threadIdx.x - 8;
        int sidx = 1 + (t2 >> 3);
        int k    = t2 & 7;
        unsigned v = 0;
        #pragma unroll
        for (int wp = 0; wp < 8; wp++) v += ws[wp*48 + 8 + sidx*8 + k];
        #pragma unroll
        for (int j = 0; j < 4; j++)
            atomicAdd(&stats[sidx*512 + (c4*4 + j)*8 + k], (int)((v >> (8*j)) & 0xffu));
    }
    if (threadIdx.x < 128) {
        int corner = threadIdx.x >> 5;
        int l = threadIdx.x & 31;
        int j = l >> 3, k = l & 7;
        int v = (int)scCor[threadIdx.x];
        if (v) atomicAdd(&stats[(5 + corner)*512 + (c4*4 + j)*8 + k], v);
    }
}

// ---------------- int8 TENSOR-CORE conv (mma.sync m16n8k32) + BN (+identity) ----
// Weights staged TRANSPOSED: [c4][pos][gid][nt] (c4 stride 584 = 576+8 pad),
// so B fragments load as 2x LDS.128 per (pos, c4) instead of 8x LDS.32.
template<int PASS>
__global__ void __launch_bounds__(224) convKernel(
    const float* __restrict__ gamma, const float* __restrict__ beta,
    const float* __restrict__ mean,  const float* __restrict__ var,
    float* __restrict__ dOut)
{
    cudaGridDependencySynchronize();
    const unsigned* __restrict__ inP = (PASS == 1) ? g_qxp : g_q1p;
    const unsigned* __restrict__ wP  = (PASS == 1) ? g_qw1p : g_qw2p;
    int n  = blockIdx.x / 28;
    int h0 = (blockIdx.x - n*28) * 2;

    extern __shared__ unsigned dynS[];
    unsigned* sW  = dynS;            // 16*584 = 9344 words (transposed weights)
    unsigned* sIn = dynS + 9344;     // 16*232 = 3712 words
    __shared__ float sAc[64], sBc[64];
    __shared__ float smx[7];

    int tid  = threadIdx.x;
    int lane = tid & 31, wid = tid >> 5;
    int gid  = lane >> 2, t4 = lane & 3;
    int w0   = wid * 8;

    float sp1, sx = 0.f;
    if (PASS == 1) {
        sp1 = (g_maxabs_x * (1.f/127.f)) * (g_maxw1 * (1.f/127.f));
    } else {
        sp1 = (g_max_r1 * (1.f/255.f)) * (g_maxw2 * (1.f/127.f));
        sx  = g_maxabs_x * (1.f/127.f);
    }
    if (tid < 64) {
        float inv = gamma[tid] / sqrtf(var[tid] + 1e-5f);
        sAc[tid] = sp1 * inv;
        sBc[tid] = beta[tid] - mean[tid]*inv;
    }

    // stage weights transposed: dest word = c4*584 + pos*64 + (o&7)*8 + (o>>3)
    {
        const uint4* wp4 = (const uint4*)wP;
        for (int i4 = tid; i4 < 2304; i4 += 224) {
            int i = i4 << 2;
            int o = i & 63;
            int cp = i >> 6;
            int c4l = cp / 9;
            int pos = cp - c4l*9;
            uint4 v = wp4[i4];
            unsigned base = c4l*584 + pos*64 + (o >> 3);
            int og = o & 7;      // 0 or 4
            sW[base + (og + 0)*8] = v.x;
            sW[base + (og + 1)*8] = v.y;
            sW[base + (og + 2)*8] = v.z;
            sW[base + (og + 3)*8] = v.w;
        }
    }
    // stage input tile (rows h0-1 .. h0+2 with halo)
    for (int p = tid; p < 3712; p += 224) {
        int c4r = p / 58;
        int cc  = p - c4r*58;
        int rr  = c4r & 3;
        int c4l = c4r >> 2;
        int gr = h0 - 1 + rr, gc = cc - 1;
        unsigned v = 0;
        if ((unsigned)gr < 56u && (unsigned)gc < 56u)
            v = inP[(n*16 + c4l)*HW + gr*WID + gc];
        sIn[c4l*232 + rr*58 + cc] = v;
    }
    __syncthreads();

    int acc[8][4];
    #pragma unroll
    for (int nt = 0; nt < 8; nt++)
        #pragma unroll
        for (int r = 0; r < 4; r++) acc[nt][r] = 0;

    #pragma unroll
    for (int cg = 0; cg < 2; cg++) {
        int cb = cg * 8;
        #pragma unroll
        for (int ph = 0; ph < 3; ph++) {
            #pragma unroll
            for (int pw = 0; pw < 3; pw++) {
                int pos = ph*3 + pw;
                int ccol = w0 + gid + pw;
                unsigned a0 = sIn[(cb + t4    )*232 +  ph   *58 + ccol];
                unsigned a1 = sIn[(cb + t4    )*232 + (ph+1)*58 + ccol];
                unsigned a2 = sIn[(cb + 4 + t4)*232 +  ph   *58 + ccol];
                unsigned a3 = sIn[(cb + 4 + t4)*232 + (ph+1)*58 + ccol];
                const uint4* pb0 = (const uint4*)(sW + (cb + t4    )*584 + pos*64 + gid*8);
                const uint4* pb1 = (const uint4*)(sW + (cb + 4 + t4)*584 + pos*64 + gid*8);
                uint4 b0lo = pb0[0], b0hi = pb0[1];
                uint4 b1lo = pb1[0], b1hi = pb1[1];
                unsigned b0a[8] = {b0lo.x, b0lo.y, b0lo.z, b0lo.w, b0hi.x, b0hi.y, b0hi.z, b0hi.w};
                unsigned b1a[8] = {b1lo.x, b1lo.y, b1lo.z, b1lo.w, b1hi.x, b1hi.y, b1hi.z, b1hi.w};
                #pragma unroll
                for (int nt = 0; nt < 8; nt++)
                    MMA8<PASS>(acc[nt], a0, a1, a2, a3, b0a[nt], b1a[nt]);
            }
        }
    }

    // epilogue: BN (+identity), store, max
    float* dstp = (PASS == 1) ? g_t1 : dOut;
    int hw0 = h0*WID + w0 + gid;
    int hw1 = hw0 + WID;
    float mx = 0.f;
    #pragma unroll
    for (int nt = 0; nt < 8; nt++) {
        int o0 = nt*8 + t4*2;
        float A0 = sAc[o0],   B0 = sBc[o0];
        float A1 = sAc[o0+1], B1 = sBc[o0+1];
        float t00 = (float)acc[nt][0] * A0 + B0;
        float t01 = (float)acc[nt][1] * A1 + B1;
        float t10 = (float)acc[nt][2] * A0 + B0;
        float t11 = (float)acc[nt][3] * A1 + B1;
        if (PASS == 2) {
            int c4i = o0 >> 2;
            int sh  = (o0 & 3) * 8;
            unsigned id0 = g_qxp[(n*16 + c4i)*HW + hw0];
            unsigned id1 = g_qxp[(n*16 + c4i)*HW + hw1];
            t00 += (float)((int)(int8_t)((id0 >> sh)     & 0xffu)) * sx;
            t01 += (float)((int)(int8_t)((id0 >> (sh+8)) & 0xffu)) * sx;
            t10 += (float)((int)(int8_t)((id1 >> sh)     & 0xffu)) * sx;
            t11 += (float)((int)(int8_t)((id1 >> (sh+8)) & 0xffu)) * sx;
        }
        dstp[(n*CC + o0    )*HW + hw0] = t00;
        dstp[(n*CC + o0 + 1)*HW + hw0] = t01;
        dstp[(n*CC + o0    )*HW + hw1] = t10;
        dstp[(n*CC + o0 + 1)*HW + hw1] = t11;
        mx = fmaxf(mx, fmaxf(fmaxf(t00, t01), fmaxf(t10, t11)));
    }
    mx = warpMaxPos(mx);
    if (lane == 0) smx[wid] = mx;
    __syncthreads();
    if (tid == 0) {
        float m = smx[0];
        #pragma unroll
        for (int i = 1; i < 7; i++) m = fmaxf(m, smx[i]);
        atomicMaxF((PASS == 1) ? &g_max_r1 : &g_max_r2, m);
    }
}

// ---------------- HM_act / HM_energy from factorized stats ----------------
__device__ __forceinline__ long long energyFor(const int* stats, const int* wsum, int cb) {
    int S   = stats[        cb];
    int r0  = stats[ 512  + cb];
    int r55 = stats[1024  + cb];
    int c0  = stats[1536  + cb];
    int c55 = stats[2048  + cb];
    int s00 = stats[2560  + cb];
    int s0b = stats[3072  + cb];
    int sb0 = stats[3584  + cb];
    int sbb = stats[4096  + cb];
    long long en = 0;
    #pragma unroll
    for (int kh = 0; kh < 3; kh++) {
        #pragma unroll
        for (int kw = 0; kw < 3; kw++) {
            int xs = S;
            if (kh == 2) xs -= r0;  else if (kh == 0) xs -= r55;
            if (kw == 2) xs -= c0;  else if (kw == 0) xs -= c55;
            if (kh == 2 && kw == 2) xs += s00;
            if (kh == 2 && kw == 0) xs += s0b;
            if (kh == 0 && kw == 2) xs += sb0;
            if (kh == 0 && kw == 0) xs += sbb;
            en += (long long)wsum[cb*9 + kh*3 + kw] * (long long)xs;
        }
    }
    return en;
}

// ---------------- final QuantReLU on d_out (in place) + finalize (block 1568) --
__global__ void __launch_bounds__(256) finalQuantFin(float* __restrict__ out) {
    cudaGridDependencySynchronize();
    if (blockIdx.x == 1568) {
        int t = threadIdx.x;
        long long act = 0, en = 0;
        for (int cb = t; cb < 512; cb += 256) {
            act += (long long)g_stats1[cb] + (long long)g_stats2[cb];
            en  += energyFor(g_stats1, g_wsum1, cb) + energyFor(g_stats2, g_wsum2, cb);
        }
        __shared__ long long sa[256], se[256];
        sa[t] = act; se[t] = en;
        __syncthreads();
        for (int step = 128; step; step >>= 1) {
            if (t < step) { sa[t] += sa[t + step]; se[t] += se[t + step]; }
            __syncthreads();
        }
        if (t == 0) {
            out[NN*CC*HW    ] = (float)sa[0];   // HM_act
            out[NN*CC*HW + 1] = (float)se[0];   // HM_energy
        }
        return;
    }
    float s = g_max_r2 * (1.f/255.f);
    float sinv = 1.0f / s;
    float4* o4 = (float4*)out;
    int base = blockIdx.x*256 + threadIdx.x;
    #pragma unroll
    for (int it = 0; it < 2; it++) {
        int i = base + it*401408;
        float4 v = o4[i];
        v.x = (float)::min(255, __float2int_rn(fmaxf(v.x, 0.f) * sinv)) * s;
        v.y = (float)::min(255, __float2int_rn(fmaxf(v.y, 0.f) * sinv)) * s;
        v.z = (float)::min(255, __float2int_rn(fmaxf(v.z, 0.f) * sinv)) * s;
        v.w = (float)::min(255, __float2int_rn(fmaxf(v.w, 0.f) * sinv)) * s;
        o4[i] = v;
    }
}

// ---------------- PDL launch helper ----------------
template <typename F, typename... Args>
static inline void launchPDL(F f, unsigned grid, unsigned block, unsigned smem, Args... args) {
    cudaLaunchConfig_t cfg = {};
    cfg.gridDim  = dim3(grid, 1, 1);
    cfg.blockDim = dim3(block, 1, 1);
    cfg.dynamicSmemBytes = smem;
    cudaLaunchAttribute at[1];
    at[0].id = cudaLaunchAttributeProgrammaticStreamSerialization;
    at[0].val.programmaticStreamSerializationAllowed = 1;
    cfg.attrs = at;
    cfg.numAttrs = 1;
    cfg.stream = 0;
    cudaLaunchKernelEx(&cfg, f, args...);
}

#define CONV_SMEM ((9344 + 3712) * 4)

// ---------------- launch ----------------
extern "C" void kernel_launch(void* const* d_in, const int* in_sizes, int n_in,
                              void* d_out, int out_size) {
    const float* x  = (const float*)d_in[0];
    const float* w1 = (const float*)d_in[1];
    const float* w2 = (const float*)d_in[2];
    const float* g1 = (const float*)d_in[3];
    const float* b1 = (const float*)d_in[4];
    const float* m1 = (const float*)d_in[5];
    const float* v1 = (const float*)d_in[6];
    const float* g2 = (const float*)d_in[7];
    const float* b2 = (const float*)d_in[8];
    const float* m2 = (const float*)d_in[9];
    const float* v2 = (const float*)d_in[10];
    float* out = (float*)d_out;

    cudaFuncSetAttribute(convKernel<1>, cudaFuncAttributeMaxDynamicSharedMemorySize, CONV_SMEM);
    cudaFuncSetAttribute(convKernel<2>, cudaFuncAttributeMaxDynamicSharedMemorySize, CONV_SMEM);

    reduceA<<<515, 256>>>((const float4*)x, w1, w2);
    launchPDL(quantStatsKernel<1>, 548, 256, 0, x, w1, w2);
    launchPDL(convKernel<1>, 448, 224, CONV_SMEM, g1, b1, m1, v1, (float*)nullptr);
    launchPDL(quantStatsKernel<2>, 512, 256, 0, (const float*)nullptr, (const float*)nullptr, (const float*)nullptr);
    launchPDL(convKernel<2>, 448, 224, CONV_SMEM, g2, b2, m2, v2, out);
    launchPDL(finalQuantFin, 1569, 256, 0, out);
}